// round 4
// baseline (speedup 1.0000x reference)
#include <cuda_runtime.h>
#include <cstdint>
#include <cfloat>

#define NHEADS 16
#define BATCH  2
#define SEQ    2048
#define CDIM   1024
#define HDIM   64
#define MROWS  (BATCH*SEQ)   // 4096

// ---------------- scratch (device globals; no allocations allowed) ----------
__device__ float g_qkv[(size_t)MROWS * 3 * CDIM];                 // 48 MB
__device__ float g_q[(size_t)BATCH * NHEADS * SEQ * HDIM];        // 16 MB
__device__ float g_k[(size_t)BATCH * NHEADS * SEQ * HDIM];        // 16 MB
__device__ float g_v[(size_t)BATCH * NHEADS * SEQ * HDIM];        // 16 MB
__device__ float g_o[(size_t)MROWS * CDIM];                       // 16 MB

// ---------------- tiled fp32 NT GEMM: C[M,N] = A[M,K] * B[N,K]^T (+bias) ----
// BM=BN=128, BK=8, 256 threads, 8x8 micro-tile per thread.
__global__ __launch_bounds__(256) void sgemm_nt(
    const float* __restrict__ A, const float* __restrict__ B,
    const float* __restrict__ bias, float* __restrict__ C,
    int M, int N, int K)
{
    __shared__ float As[8][128];
    __shared__ float Bs[8][128];
    int tid = threadIdx.x;
    int tx = tid & 15, ty = tid >> 4;
    int bm = blockIdx.y << 7, bn = blockIdx.x << 7;
    int lrow = tid >> 1;            // 0..127
    int lk   = (tid & 1) << 2;      // 0 or 4
    const float* Ap = A + (size_t)(bm + lrow) * K + lk;
    const float* Bp = B + (size_t)(bn + lrow) * K + lk;

    float acc[8][8];
#pragma unroll
    for (int i = 0; i < 8; i++)
#pragma unroll
        for (int j = 0; j < 8; j++) acc[i][j] = 0.f;

    for (int k0 = 0; k0 < K; k0 += 8) {
        float4 a4 = *(const float4*)(Ap + k0);
        float4 b4 = *(const float4*)(Bp + k0);
        __syncthreads();   // previous compute phase done before smem overwrite
        As[lk+0][lrow] = a4.x; As[lk+1][lrow] = a4.y;
        As[lk+2][lrow] = a4.z; As[lk+3][lrow] = a4.w;
        Bs[lk+0][lrow] = b4.x; Bs[lk+1][lrow] = b4.y;
        Bs[lk+2][lrow] = b4.z; Bs[lk+3][lrow] = b4.w;
        __syncthreads();
#pragma unroll
        for (int kk = 0; kk < 8; kk++) {
            float4 a0 = *(const float4*)&As[kk][ty*8];
            float4 a1 = *(const float4*)&As[kk][ty*8+4];
            float4 b0 = *(const float4*)&Bs[kk][tx*8];
            float4 b1 = *(const float4*)&Bs[kk][tx*8+4];
            float a[8] = {a0.x,a0.y,a0.z,a0.w,a1.x,a1.y,a1.z,a1.w};
            float b[8] = {b0.x,b0.y,b0.z,b0.w,b1.x,b1.y,b1.z,b1.w};
#pragma unroll
            for (int i = 0; i < 8; i++)
#pragma unroll
                for (int j = 0; j < 8; j++) acc[i][j] += a[i]*b[j];
        }
    }

    float bz[8];
#pragma unroll
    for (int j = 0; j < 8; j++) bz[j] = bias ? bias[bn + tx*8 + j] : 0.f;
#pragma unroll
    for (int i = 0; i < 8; i++) {
        int row = bm + ty*8 + i;
        float* Cp = C + (size_t)row * N + bn + tx*8;
        *(float4*)Cp     = make_float4(acc[i][0]+bz[0], acc[i][1]+bz[1],
                                       acc[i][2]+bz[2], acc[i][3]+bz[3]);
        *(float4*)(Cp+4) = make_float4(acc[i][4]+bz[4], acc[i][5]+bz[5],
                                       acc[i][6]+bz[6], acc[i][7]+bz[7]);
    }
}

// ---------------- per-head LayerNorm on Q,K + split into [B,H,N,d] ---------
// one warp handles one (row m, head h); lane covers dd and dd+32.
__global__ __launch_bounds__(256) void ln_split(
    const float* __restrict__ qkv,
    const float* __restrict__ qg, const float* __restrict__ qb,
    const float* __restrict__ kg, const float* __restrict__ kb,
    float* __restrict__ Q, float* __restrict__ K, float* __restrict__ V)
{
    int gw = (blockIdx.x * 256 + threadIdx.x) >> 5;
    int lane = threadIdx.x & 31;
    if (gw >= MROWS * NHEADS) return;
    int m = gw >> 4, h = gw & 15;
    int b = m >> 11, n = m & 2047;
    const float* row = qkv + (size_t)m * (3*CDIM);
    size_t obase = ((size_t)(b*NHEADS + h) * SEQ + n) * HDIM;

    // Q
    {
        float v0 = row[h*64 + lane], v1 = row[h*64 + 32 + lane];
        float s = v0 + v1, ss = v0*v0 + v1*v1;
#pragma unroll
        for (int o = 16; o > 0; o >>= 1) {
            s  += __shfl_xor_sync(0xffffffffu, s,  o);
            ss += __shfl_xor_sync(0xffffffffu, ss, o);
        }
        float mu  = s * (1.f/64.f);
        float var = ss * (1.f/64.f) - mu*mu;
        float r = rsqrtf(var + 1e-5f);
        Q[obase + lane]      = (v0-mu)*r*qg[lane]    + qb[lane];
        Q[obase + 32 + lane] = (v1-mu)*r*qg[32+lane] + qb[32+lane];
    }
    // K (columns offset by CDIM)
    {
        float v0 = row[CDIM + h*64 + lane], v1 = row[CDIM + h*64 + 32 + lane];
        float s = v0 + v1, ss = v0*v0 + v1*v1;
#pragma unroll
        for (int o = 16; o > 0; o >>= 1) {
            s  += __shfl_xor_sync(0xffffffffu, s,  o);
            ss += __shfl_xor_sync(0xffffffffu, ss, o);
        }
        float mu  = s * (1.f/64.f);
        float var = ss * (1.f/64.f) - mu*mu;
        float r = rsqrtf(var + 1e-5f);
        K[obase + lane]      = (v0-mu)*r*kg[lane]    + kb[lane];
        K[obase + 32 + lane] = (v1-mu)*r*kg[32+lane] + kb[32+lane];
    }
    // V copy (columns offset by 2*CDIM)
    V[obase + lane]      = row[2*CDIM + h*64 + lane];
    V[obase + 32 + lane] = row[2*CDIM + h*64 + 32 + lane];
}

// ---------------- flash attention, fp32, BQ=BK=64, d=64 --------------------
// 256 threads as 16x16, 4x4 micro-tile. Online softmax. mask honored.
// smem: Qs[d][r] (prescaled), KPs[d][c] (reused as P[k][r]), Vs[k][c], Ms[r][c]
__global__ __launch_bounds__(256) void flash_attn(
    const float* __restrict__ Q, const float* __restrict__ K,
    const float* __restrict__ V, const unsigned char* __restrict__ mask,
    float* __restrict__ O)
{
    extern __shared__ float sm[];
    float* Qs  = sm;               // 64 x 68
    float* KPs = Qs  + 64*68;      // 64 x 68
    float* Vs  = KPs + 64*68;      // 64 x 68
    unsigned char* Ms = (unsigned char*)(Vs + 64*68);  // 64 x 64 bytes

    int tid = threadIdx.x;
    int tx = tid & 15, ty = tid >> 4;
    int qt = blockIdx.x, h = blockIdx.y, b = blockIdx.z;
    int q0 = qt * 64;
    const float scale = 0.125f;    // d^-0.5

    const float* Qg = Q + ((size_t)(b*NHEADS + h)*SEQ + q0)*HDIM;
    const float* Kg = K + (size_t)(b*NHEADS + h)*SEQ*HDIM;
    const float* Vg = V + (size_t)(b*NHEADS + h)*SEQ*HDIM;
    const unsigned char* Mg = mask + ((size_t)b*SEQ + q0)*SEQ;

    // load Q tile transposed + prescaled
    for (int base = tid*4; base < 4096; base += 1024) {
        int r = base >> 6, dd = base & 63;
        float4 v = *(const float4*)(Qg + base);
        Qs[(dd+0)*68 + r] = v.x * scale;
        Qs[(dd+1)*68 + r] = v.y * scale;
        Qs[(dd+2)*68 + r] = v.z * scale;
        Qs[(dd+3)*68 + r] = v.w * scale;
    }

    float o[4][4], mi[4], li[4];
#pragma unroll
    for (int i = 0; i < 4; i++) {
        mi[i] = -FLT_MAX; li[i] = 0.f;
#pragma unroll
        for (int j = 0; j < 4; j++) o[i][j] = 0.f;
    }

    for (int kt = 0; kt < SEQ/64; kt++) {
        const float* Kt = Kg + kt*4096;
        const float* Vt = Vg + kt*4096;
        for (int base = tid*4; base < 4096; base += 1024) {
            int r = base >> 6, dd = base & 63;
            float4 kv = *(const float4*)(Kt + base);
            KPs[(dd+0)*68 + r] = kv.x;
            KPs[(dd+1)*68 + r] = kv.y;
            KPs[(dd+2)*68 + r] = kv.z;
            KPs[(dd+3)*68 + r] = kv.w;
            float4 vv = *(const float4*)(Vt + base);
            *(float4*)&Vs[r*68 + dd] = vv;
        }
        {   // mask tile: 4096 bytes, one uint4 per thread
            int r = tid >> 2, c = (tid & 3) << 4;
            *(uint4*)&Ms[r*64 + c] = *(const uint4*)(Mg + (size_t)r*SEQ + kt*64 + c);
        }
        __syncthreads();

        // S = (scaled Q) K^T
        float s[4][4];
#pragma unroll
        for (int i = 0; i < 4; i++)
#pragma unroll
            for (int j = 0; j < 4; j++) s[i][j] = 0.f;
#pragma unroll 8
        for (int dd = 0; dd < 64; dd++) {
            float4 qa = *(const float4*)&Qs[dd*68 + ty*4];
            float4 kb = *(const float4*)&KPs[dd*68 + tx*4];
            float qv[4] = {qa.x,qa.y,qa.z,qa.w};
            float kv[4] = {kb.x,kb.y,kb.z,kb.w};
#pragma unroll
            for (int i = 0; i < 4; i++)
#pragma unroll
                for (int j = 0; j < 4; j++) s[i][j] += qv[i]*kv[j];
        }
        // mask (mask==true -> -FLT_MAX, matching jnp.where(mask, -finfo.max, .))
#pragma unroll
        for (int i = 0; i < 4; i++)
#pragma unroll
            for (int j = 0; j < 4; j++)
                if (Ms[(ty*4+i)*64 + tx*4+j]) s[i][j] = -FLT_MAX;

        // online softmax (row reductions across the 16 tx lanes of each row)
#pragma unroll
        for (int i = 0; i < 4; i++) {
            float v = fmaxf(fmaxf(s[i][0], s[i][1]), fmaxf(s[i][2], s[i][3]));
#pragma unroll
            for (int off = 8; off > 0; off >>= 1)
                v = fmaxf(v, __shfl_xor_sync(0xffffffffu, v, off));
            float mnew = fmaxf(mi[i], v);
            float al = __expf(mi[i] - mnew);
            float sum = 0.f;
#pragma unroll
            for (int j = 0; j < 4; j++) {
                s[i][j] = __expf(s[i][j] - mnew);
                sum += s[i][j];
            }
#pragma unroll
            for (int off = 8; off > 0; off >>= 1)
                sum += __shfl_xor_sync(0xffffffffu, sum, off);
            li[i] = li[i]*al + sum;
            mi[i] = mnew;
#pragma unroll
            for (int j = 0; j < 4; j++) o[i][j] *= al;
        }
        __syncthreads();   // done reading KPs as K-tile

        // store P transposed into KPs: P[k][r]
#pragma unroll
        for (int i = 0; i < 4; i++)
#pragma unroll
            for (int j = 0; j < 4; j++)
                KPs[(tx*4+j)*68 + ty*4+i] = s[i][j];
        __syncthreads();

        // O += P V
#pragma unroll 8
        for (int kk = 0; kk < 64; kk++) {
            float4 pa = *(const float4*)&KPs[kk*68 + ty*4];
            float4 vb = *(const float4*)&Vs[kk*68 + tx*4];
            float pv[4] = {pa.x,pa.y,pa.z,pa.w};
            float vv[4] = {vb.x,vb.y,vb.z,vb.w};
#pragma unroll
            for (int i = 0; i < 4; i++)
#pragma unroll
                for (int j = 0; j < 4; j++) o[i][j] += pv[i]*vv[j];
        }
        __syncthreads();   // before next tile overwrites KPs/Vs
    }

    // write O in [B,N,H,d] layout (== rows of the [4096,1024] proj input)
#pragma unroll
    for (int i = 0; i < 4; i++) {
        float inv = 1.f / li[i];
        int n = q0 + ty*4 + i;
        float* Op = O + (((size_t)b*SEQ + n)*NHEADS + h)*HDIM + tx*4;
        *(float4*)Op = make_float4(o[i][0]*inv, o[i][1]*inv,
                                   o[i][2]*inv, o[i][3]*inv);
    }
}

// ---------------- launch ----------------------------------------------------
extern "C" void kernel_launch(void* const* d_in, const int* in_sizes, int n_in,
                              void* d_out, int out_size)
{
    const float*         x       = (const float*)d_in[0];
    const unsigned char* mask    = (const unsigned char*)d_in[1];
    const float*         w_qkv   = (const float*)d_in[2];
    const float*         w_proj  = (const float*)d_in[3];
    const float*         b_proj  = (const float*)d_in[4];
    const float*         q_gamma = (const float*)d_in[5];
    const float*         q_beta  = (const float*)d_in[6];
    const float*         k_gamma = (const float*)d_in[7];
    const float*         k_beta  = (const float*)d_in[8];
    float* out = (float*)d_out;

    float *qkv, *q, *k, *v, *o;
    cudaGetSymbolAddress((void**)&qkv, g_qkv);
    cudaGetSymbolAddress((void**)&q,   g_q);
    cudaGetSymbolAddress((void**)&k,   g_k);
    cudaGetSymbolAddress((void**)&v,   g_v);
    cudaGetSymbolAddress((void**)&o,   g_o);

    // 1) QKV GEMM: [4096,1024] x [3072,1024]^T -> [4096,3072]
    sgemm_nt<<<dim3(3*CDIM/128, MROWS/128), 256>>>(
        x, w_qkv, nullptr, qkv, MROWS, 3*CDIM, CDIM);

    // 2) LN(q), LN(k), split into [B,H,N,d]
    ln_split<<<(MROWS*NHEADS*32)/256, 256>>>(
        qkv, q_gamma, q_beta, k_gamma, k_beta, q, k, v);

    // 3) flash attention -> [B,N,H,d]
    int smem = 3*64*68*(int)sizeof(float) + 64*64;   // 56320 B
    cudaFuncSetAttribute(flash_attn,
                         cudaFuncAttributeMaxDynamicSharedMemorySize, smem);
    flash_attn<<<dim3(SEQ/64, NHEADS, BATCH), 256, smem>>>(q, k, v, mask, o);

    // 4) proj GEMM + bias: [4096,1024] x [1024,1024]^T -> out
    sgemm_nt<<<dim3(CDIM/128, MROWS/128), 256>>>(
        o, w_proj, b_proj, out, MROWS, CDIM, CDIM);
}

// round 5
// speedup vs baseline: 1.3721x; 1.3721x over previous
#include <cuda_runtime.h>
#include <cuda_bf16.h>
#include <cstdint>
#include <cfloat>

#define NHEADS 16
#define BATCH  2
#define SEQ    2048
#define CDIM   1024
#define HDIM   64
#define MROWS  (BATCH*SEQ)   // 4096

// ---------------- scratch (device globals; no allocations allowed) ----------
__device__ float g_qkv[(size_t)MROWS * 3 * CDIM];                 // 48 MB
__device__ float g_q[(size_t)BATCH * NHEADS * SEQ * HDIM];
__device__ float g_k[(size_t)BATCH * NHEADS * SEQ * HDIM];
__device__ float g_v[(size_t)BATCH * NHEADS * SEQ * HDIM];
__device__ float g_o[(size_t)MROWS * CDIM];

// bf16 hi/lo split scratch
__device__ __nv_bfloat16 g_xh[(size_t)MROWS * CDIM];
__device__ __nv_bfloat16 g_xl[(size_t)MROWS * CDIM];
__device__ __nv_bfloat16 g_wqh[(size_t)3 * CDIM * CDIM];
__device__ __nv_bfloat16 g_wql[(size_t)3 * CDIM * CDIM];
__device__ __nv_bfloat16 g_wph[(size_t)CDIM * CDIM];
__device__ __nv_bfloat16 g_wpl[(size_t)CDIM * CDIM];
__device__ __nv_bfloat16 g_oh[(size_t)MROWS * CDIM];
__device__ __nv_bfloat16 g_ol[(size_t)MROWS * CDIM];

// ---------------- fp32 -> (hi, lo) bf16 split, vectorized -------------------
__global__ __launch_bounds__(256) void cvt_split(
    const float* __restrict__ in, __nv_bfloat16* __restrict__ hi,
    __nv_bfloat16* __restrict__ lo, int n)
{
    int i = (blockIdx.x * 256 + threadIdx.x) * 4;
    if (i >= n) return;
    float4 v = *(const float4*)(in + i);
    float vv[4] = {v.x, v.y, v.z, v.w};
    union { __nv_bfloat16 b[4]; uint2 u; } H, L;
#pragma unroll
    for (int j = 0; j < 4; j++) {
        __nv_bfloat16 h = __float2bfloat16(vv[j]);          // round-to-nearest
        float r = vv[j] - __bfloat162float(h);
        H.b[j] = h;
        L.b[j] = __float2bfloat16(r);
    }
    *(uint2*)(hi + i) = H.u;
    *(uint2*)(lo + i) = L.u;
}

// ---------------- bf16x3 split-precision MMA GEMM ---------------------------
// C[M,N] = A[M,K] * B[N,K]^T (+bias), fp32-accurate via hi/lo bf16 split.
// BM=BN=128, BK=32, 256 threads = 8 warps (warp grid 4m x 2n, warp tile 32x64).
#define BM 128
#define BN 128
#define BK 32
#define SST 40                       // smem row stride (elements), bank-safe
#define MATE (128 * SST)             // elements per matrix tile in smem

__device__ __forceinline__ void cp16(void* s, const void* g) {
    uint32_t sa = (uint32_t)__cvta_generic_to_shared(s);
    asm volatile("cp.async.cg.shared.global [%0], [%1], 16;" :: "r"(sa), "l"(g));
}
__device__ __forceinline__ void cp_commit() { asm volatile("cp.async.commit_group;"); }
__device__ __forceinline__ void cp_wait0()  { asm volatile("cp.async.wait_group 0;"); }

__device__ __forceinline__ void ldm4(uint32_t* r, const void* p) {
    uint32_t a = (uint32_t)__cvta_generic_to_shared(p);
    asm volatile("ldmatrix.sync.aligned.m8n8.x4.shared.b16 {%0,%1,%2,%3}, [%4];"
                 : "=r"(r[0]), "=r"(r[1]), "=r"(r[2]), "=r"(r[3]) : "r"(a));
}
__device__ __forceinline__ void mma_bf16(float* c, const uint32_t* a, const uint32_t* b) {
    asm volatile("mma.sync.aligned.m16n8k16.row.col.f32.bf16.bf16.f32 "
                 "{%0,%1,%2,%3}, {%4,%5,%6,%7}, {%8,%9}, {%0,%1,%2,%3};"
                 : "+f"(c[0]), "+f"(c[1]), "+f"(c[2]), "+f"(c[3])
                 : "r"(a[0]), "r"(a[1]), "r"(a[2]), "r"(a[3]),
                   "r"(b[0]), "r"(b[1]));
}

__global__ __launch_bounds__(256, 1) void mma_gemm_nt(
    const __nv_bfloat16* __restrict__ Ah, const __nv_bfloat16* __restrict__ Al,
    const __nv_bfloat16* __restrict__ Bh, const __nv_bfloat16* __restrict__ Bl,
    const float* __restrict__ bias, float* __restrict__ C,
    int M, int N, int K)
{
    extern __shared__ __nv_bfloat16 smg[];
    int tid = threadIdx.x, lane = tid & 31, wid = tid >> 5;
    int wm = wid & 3, wn = wid >> 2;
    int bm = blockIdx.y * BM, bn = blockIdx.x * BN;

    float acc[2][8][4];
#pragma unroll
    for (int t = 0; t < 2; t++)
#pragma unroll
        for (int nn = 0; nn < 8; nn++)
#pragma unroll
            for (int q = 0; q < 4; q++) acc[t][nn][q] = 0.f;

    auto load_stage = [&](int st, int k0) {
        __nv_bfloat16* base = smg + st * 4 * MATE;
#pragma unroll
        for (int i = 0; i < 2; i++) {
            int c = tid + i * 256;
            int row = c >> 2, ch = (c & 3) * 8;
            int so = row * SST + ch;
            size_t goA = (size_t)(bm + row) * K + k0 + ch;
            size_t goB = (size_t)(bn + row) * K + k0 + ch;
            cp16(base + so,            Ah + goA);
            cp16(base + MATE + so,     Al + goA);
            cp16(base + 2 * MATE + so, Bh + goB);
            cp16(base + 3 * MATE + so, Bl + goB);
        }
    };

    load_stage(0, 0);
    cp_commit();

    // fragment row mappings (fixed per lane)
    int mrow = (lane & 7) + ((lane >> 3) & 1) * 8;
    int kcA  = (lane >> 4) * 8;
    int nrow = (lane & 7) + ((lane >> 4) & 1) * 8;
    int kcB  = ((lane >> 3) & 1) * 8;

    int nst = K / BK;
    for (int s = 0; s < nst; s++) {
        cp_wait0();
        __syncthreads();
        if (s + 1 < nst) { load_stage((s + 1) & 1, (s + 1) * BK); cp_commit(); }
        __nv_bfloat16* base = smg + (s & 1) * 4 * MATE;

#pragma unroll
        for (int kk = 0; kk < BK; kk += 16) {
            uint32_t ahf[2][4], alf[2][4];
#pragma unroll
            for (int t = 0; t < 2; t++) {
                const __nv_bfloat16* pa =
                    base + (wm * 32 + t * 16 + mrow) * SST + kk + kcA;
                ldm4(ahf[t], pa);
                ldm4(alf[t], pa + MATE);
            }
            uint32_t bhf[8][2], blf[8][2];
#pragma unroll
            for (int p = 0; p < 4; p++) {
                const __nv_bfloat16* pb =
                    base + 2 * MATE + (wn * 64 + p * 16 + nrow) * SST + kk + kcB;
                uint32_t r[4];
                ldm4(r, pb);
                bhf[2*p][0] = r[0]; bhf[2*p][1] = r[1];
                bhf[2*p+1][0] = r[2]; bhf[2*p+1][1] = r[3];
                ldm4(r, pb + MATE);
                blf[2*p][0] = r[0]; blf[2*p][1] = r[1];
                blf[2*p+1][0] = r[2]; blf[2*p+1][1] = r[3];
            }
#pragma unroll
            for (int t = 0; t < 2; t++)
#pragma unroll
                for (int nn = 0; nn < 8; nn++) {
                    mma_bf16(acc[t][nn], ahf[t], bhf[nn]);  // hi*hi
                    mma_bf16(acc[t][nn], alf[t], bhf[nn]);  // lo*hi
                    mma_bf16(acc[t][nn], ahf[t], blf[nn]);  // hi*lo
                }
        }
    }

    // epilogue
    int r0 = bm + wm * 32 + (lane >> 2);
    int c0 = bn + wn * 64 + (lane & 3) * 2;
#pragma unroll
    for (int t = 0; t < 2; t++) {
        int row = r0 + t * 16;
#pragma unroll
        for (int nn = 0; nn < 8; nn++) {
            int col = c0 + nn * 8;
            float b0 = bias ? bias[col] : 0.f;
            float b1 = bias ? bias[col + 1] : 0.f;
            *(float2*)(C + (size_t)row * N + col) =
                make_float2(acc[t][nn][0] + b0, acc[t][nn][1] + b1);
            *(float2*)(C + (size_t)(row + 8) * N + col) =
                make_float2(acc[t][nn][2] + b0, acc[t][nn][3] + b1);
        }
    }
}

// ---------------- per-head LayerNorm on Q,K + split into [B,H,N,d] ---------
__global__ __launch_bounds__(256) void ln_split(
    const float* __restrict__ qkv,
    const float* __restrict__ qg, const float* __restrict__ qb,
    const float* __restrict__ kg, const float* __restrict__ kb,
    float* __restrict__ Q, float* __restrict__ K, float* __restrict__ V)
{
    int gw = (blockIdx.x * 256 + threadIdx.x) >> 5;
    int lane = threadIdx.x & 31;
    if (gw >= MROWS * NHEADS) return;
    int m = gw >> 4, h = gw & 15;
    int b = m >> 11, n = m & 2047;
    const float* row = qkv + (size_t)m * (3 * CDIM);
    size_t obase = ((size_t)(b * NHEADS + h) * SEQ + n) * HDIM;

    {
        float v0 = row[h * 64 + lane], v1 = row[h * 64 + 32 + lane];
        float s = v0 + v1, ss = v0 * v0 + v1 * v1;
#pragma unroll
        for (int o = 16; o > 0; o >>= 1) {
            s  += __shfl_xor_sync(0xffffffffu, s,  o);
            ss += __shfl_xor_sync(0xffffffffu, ss, o);
        }
        float mu  = s * (1.f / 64.f);
        float var = ss * (1.f / 64.f) - mu * mu;
        float r = rsqrtf(var + 1e-5f);
        Q[obase + lane]      = (v0 - mu) * r * qg[lane]      + qb[lane];
        Q[obase + 32 + lane] = (v1 - mu) * r * qg[32 + lane] + qb[32 + lane];
    }
    {
        float v0 = row[CDIM + h * 64 + lane], v1 = row[CDIM + h * 64 + 32 + lane];
        float s = v0 + v1, ss = v0 * v0 + v1 * v1;
#pragma unroll
        for (int o = 16; o > 0; o >>= 1) {
            s  += __shfl_xor_sync(0xffffffffu, s,  o);
            ss += __shfl_xor_sync(0xffffffffu, ss, o);
        }
        float mu  = s * (1.f / 64.f);
        float var = ss * (1.f / 64.f) - mu * mu;
        float r = rsqrtf(var + 1e-5f);
        K[obase + lane]      = (v0 - mu) * r * kg[lane]      + kb[lane];
        K[obase + 32 + lane] = (v1 - mu) * r * kg[32 + lane] + kb[32 + lane];
    }
    V[obase + lane]      = row[2 * CDIM + h * 64 + lane];
    V[obase + 32 + lane] = row[2 * CDIM + h * 64 + 32 + lane];
}

// ---------------- flash attention, fp32, BQ=BK=64, d=64 --------------------
__global__ __launch_bounds__(256) void flash_attn(
    const float* __restrict__ Q, const float* __restrict__ K,
    const float* __restrict__ V, const unsigned char* __restrict__ mask,
    float* __restrict__ O)
{
    extern __shared__ float sm[];
    float* Qs  = sm;               // 64 x 68
    float* KPs = Qs  + 64 * 68;
    float* Vs  = KPs + 64 * 68;
    unsigned char* Ms = (unsigned char*)(Vs + 64 * 68);

    int tid = threadIdx.x;
    int tx = tid & 15, ty = tid >> 4;
    int qt = blockIdx.x, h = blockIdx.y, b = blockIdx.z;
    int q0 = qt * 64;
    const float scale = 0.125f;

    const float* Qg = Q + ((size_t)(b * NHEADS + h) * SEQ + q0) * HDIM;
    const float* Kg = K + (size_t)(b * NHEADS + h) * SEQ * HDIM;
    const float* Vg = V + (size_t)(b * NHEADS + h) * SEQ * HDIM;
    const unsigned char* Mg = mask + ((size_t)b * SEQ + q0) * SEQ;

    for (int base = tid * 4; base < 4096; base += 1024) {
        int r = base >> 6, dd = base & 63;
        float4 v = *(const float4*)(Qg + base);
        Qs[(dd + 0) * 68 + r] = v.x * scale;
        Qs[(dd + 1) * 68 + r] = v.y * scale;
        Qs[(dd + 2) * 68 + r] = v.z * scale;
        Qs[(dd + 3) * 68 + r] = v.w * scale;
    }

    float o[4][4], mi[4], li[4];
#pragma unroll
    for (int i = 0; i < 4; i++) {
        mi[i] = -FLT_MAX; li[i] = 0.f;
#pragma unroll
        for (int j = 0; j < 4; j++) o[i][j] = 0.f;
    }

    for (int kt = 0; kt < SEQ / 64; kt++) {
        const float* Kt = Kg + kt * 4096;
        const float* Vt = Vg + kt * 4096;
        for (int base = tid * 4; base < 4096; base += 1024) {
            int r = base >> 6, dd = base & 63;
            float4 kv = *(const float4*)(Kt + base);
            KPs[(dd + 0) * 68 + r] = kv.x;
            KPs[(dd + 1) * 68 + r] = kv.y;
            KPs[(dd + 2) * 68 + r] = kv.z;
            KPs[(dd + 3) * 68 + r] = kv.w;
            float4 vv = *(const float4*)(Vt + base);
            *(float4*)&Vs[r * 68 + dd] = vv;
        }
        {
            int r = tid >> 2, c = (tid & 3) << 4;
            *(uint4*)&Ms[r * 64 + c] = *(const uint4*)(Mg + (size_t)r * SEQ + kt * 64 + c);
        }
        __syncthreads();

        float s[4][4];
#pragma unroll
        for (int i = 0; i < 4; i++)
#pragma unroll
            for (int j = 0; j < 4; j++) s[i][j] = 0.f;
#pragma unroll 8
        for (int dd = 0; dd < 64; dd++) {
            float4 qa = *(const float4*)&Qs[dd * 68 + ty * 4];
            float4 kb = *(const float4*)&KPs[dd * 68 + tx * 4];
            float qv[4] = {qa.x, qa.y, qa.z, qa.w};
            float kv[4] = {kb.x, kb.y, kb.z, kb.w};
#pragma unroll
            for (int i = 0; i < 4; i++)
#pragma unroll
                for (int j = 0; j < 4; j++) s[i][j] += qv[i] * kv[j];
        }
#pragma unroll
        for (int i = 0; i < 4; i++)
#pragma unroll
            for (int j = 0; j < 4; j++)
                if (Ms[(ty * 4 + i) * 64 + tx * 4 + j]) s[i][j] = -FLT_MAX;

#pragma unroll
        for (int i = 0; i < 4; i++) {
            float v = fmaxf(fmaxf(s[i][0], s[i][1]), fmaxf(s[i][2], s[i][3]));
#pragma unroll
            for (int off = 8; off > 0; off >>= 1)
                v = fmaxf(v, __shfl_xor_sync(0xffffffffu, v, off));
            float mnew = fmaxf(mi[i], v);
            float al = __expf(mi[i] - mnew);
            float sum = 0.f;
#pragma unroll
            for (int j = 0; j < 4; j++) {
                s[i][j] = __expf(s[i][j] - mnew);
                sum += s[i][j];
            }
#pragma unroll
            for (int off = 8; off > 0; off >>= 1)
                sum += __shfl_xor_sync(0xffffffffu, sum, off);
            li[i] = li[i] * al + sum;
            mi[i] = mnew;
#pragma unroll
            for (int j = 0; j < 4; j++) o[i][j] *= al;
        }
        __syncthreads();

#pragma unroll
        for (int i = 0; i < 4; i++)
#pragma unroll
            for (int j = 0; j < 4; j++)
                KPs[(tx * 4 + j) * 68 + ty * 4 + i] = s[i][j];
        __syncthreads();

#pragma unroll 8
        for (int kk = 0; kk < 64; kk++) {
            float4 pa = *(const float4*)&KPs[kk * 68 + ty * 4];
            float4 vb = *(const float4*)&Vs[kk * 68 + tx * 4];
            float pv[4] = {pa.x, pa.y, pa.z, pa.w};
            float vv[4] = {vb.x, vb.y, vb.z, vb.w};
#pragma unroll
            for (int i = 0; i < 4; i++)
#pragma unroll
                for (int j = 0; j < 4; j++) o[i][j] += pv[i] * vv[j];
        }
        __syncthreads();
    }

#pragma unroll
    for (int i = 0; i < 4; i++) {
        float inv = 1.f / li[i];
        int n = q0 + ty * 4 + i;
        float* Op = O + (((size_t)b * SEQ + n) * NHEADS + h) * HDIM + tx * 4;
        *(float4*)Op = make_float4(o[i][0] * inv, o[i][1] * inv,
                                   o[i][2] * inv, o[i][3] * inv);
    }
}

// ---------------- launch ----------------------------------------------------
extern "C" void kernel_launch(void* const* d_in, const int* in_sizes, int n_in,
                              void* d_out, int out_size)
{
    const float*         x       = (const float*)d_in[0];
    const unsigned char* mask    = (const unsigned char*)d_in[1];
    const float*         w_qkv   = (const float*)d_in[2];
    const float*         w_proj  = (const float*)d_in[3];
    const float*         b_proj  = (const float*)d_in[4];
    const float*         q_gamma = (const float*)d_in[5];
    const float*         q_beta  = (const float*)d_in[6];
    const float*         k_gamma = (const float*)d_in[7];
    const float*         k_beta  = (const float*)d_in[8];
    float* out = (float*)d_out;

    float *qkv, *q, *k, *v, *o;
    __nv_bfloat16 *xh, *xl, *wqh, *wql, *wph, *wpl, *oh, *ol;
    cudaGetSymbolAddress((void**)&qkv, g_qkv);
    cudaGetSymbolAddress((void**)&q,   g_q);
    cudaGetSymbolAddress((void**)&k,   g_k);
    cudaGetSymbolAddress((void**)&v,   g_v);
    cudaGetSymbolAddress((void**)&o,   g_o);
    cudaGetSymbolAddress((void**)&xh,  g_xh);
    cudaGetSymbolAddress((void**)&xl,  g_xl);
    cudaGetSymbolAddress((void**)&wqh, g_wqh);
    cudaGetSymbolAddress((void**)&wql, g_wql);
    cudaGetSymbolAddress((void**)&wph, g_wph);
    cudaGetSymbolAddress((void**)&wpl, g_wpl);
    cudaGetSymbolAddress((void**)&oh,  g_oh);
    cudaGetSymbolAddress((void**)&ol,  g_ol);

    static bool attr_set = false;
    if (!attr_set) {
        cudaFuncSetAttribute(mma_gemm_nt,
            cudaFuncAttributeMaxDynamicSharedMemorySize, 2 * 4 * MATE * 2);
        int smem_fa = 3 * 64 * 68 * (int)sizeof(float) + 64 * 64;
        cudaFuncSetAttribute(flash_attn,
            cudaFuncAttributeMaxDynamicSharedMemorySize, smem_fa);
        attr_set = true;
    }

    // 0) fp32 -> bf16 hi/lo splits
    int nx = MROWS * CDIM;
    cvt_split<<<nx / 4 / 256, 256>>>(x, xh, xl, nx);
    int nwq = 3 * CDIM * CDIM;
    cvt_split<<<nwq / 4 / 256, 256>>>(w_qkv, wqh, wql, nwq);
    int nwp = CDIM * CDIM;
    cvt_split<<<nwp / 4 / 256, 256>>>(w_proj, wph, wpl, nwp);

    // 1) QKV GEMM (tensor cores, bf16x3): [4096,1024] x [3072,1024]^T
    mma_gemm_nt<<<dim3(3 * CDIM / BN, MROWS / BM), 256, 2 * 4 * MATE * 2>>>(
        xh, xl, wqh, wql, nullptr, qkv, MROWS, 3 * CDIM, CDIM);

    // 2) LN(q), LN(k), split into [B,H,N,d]
    ln_split<<<(MROWS * NHEADS * 32) / 256, 256>>>(
        qkv, q_gamma, q_beta, k_gamma, k_beta, q, k, v);

    // 3) flash attention -> [B,N,H,d] (fp32)
    int smem_fa = 3 * 64 * 68 * (int)sizeof(float) + 64 * 64;
    flash_attn<<<dim3(SEQ / 64, NHEADS, BATCH), 256, smem_fa>>>(q, k, v, mask, o);

    // 3b) split attention output for the proj GEMM
    cvt_split<<<nx / 4 / 256, 256>>>(o, oh, ol, nx);

    // 4) proj GEMM + bias (tensor cores, bf16x3)
    mma_gemm_nt<<<dim3(CDIM / BN, MROWS / BM), 256, 2 * 4 * MATE * 2>>>(
        oh, ol, wph, wpl, b_proj, out, MROWS, CDIM, CDIM);
}

// round 6
// speedup vs baseline: 2.5438x; 1.8539x over previous
#include <cuda_runtime.h>
#include <cuda_bf16.h>
#include <cstdint>
#include <cfloat>

#define NHEADS 16
#define BATCH  2
#define SEQ    2048
#define CDIM   1024
#define HDIM   64
#define MROWS  (BATCH*SEQ)   // 4096

// ---------------- scratch (device globals; no allocations allowed) ----------
__device__ float g_qkv[(size_t)MROWS * 3 * CDIM];                 // 48 MB
__device__ __nv_bfloat16 g_xh[(size_t)MROWS * CDIM];
__device__ __nv_bfloat16 g_xl[(size_t)MROWS * CDIM];
__device__ __nv_bfloat16 g_wqh[(size_t)3 * CDIM * CDIM];
__device__ __nv_bfloat16 g_wql[(size_t)3 * CDIM * CDIM];
__device__ __nv_bfloat16 g_wph[(size_t)CDIM * CDIM];
__device__ __nv_bfloat16 g_wpl[(size_t)CDIM * CDIM];
__device__ __nv_bfloat16 g_oh[(size_t)MROWS * CDIM];
__device__ __nv_bfloat16 g_ol[(size_t)MROWS * CDIM];
// per-head hi/lo bf16 Q,K,V in [B,H,N,d]
#define PHN ((size_t)BATCH * NHEADS * SEQ * HDIM)
__device__ __nv_bfloat16 g_qh[PHN];
__device__ __nv_bfloat16 g_ql[PHN];
__device__ __nv_bfloat16 g_kh[PHN];
__device__ __nv_bfloat16 g_kl[PHN];
__device__ __nv_bfloat16 g_vh[PHN];
__device__ __nv_bfloat16 g_vl[PHN];

// ---------------- small PTX helpers -----------------------------------------
__device__ __forceinline__ void cp16(void* s, const void* g) {
    uint32_t sa = (uint32_t)__cvta_generic_to_shared(s);
    asm volatile("cp.async.cg.shared.global [%0], [%1], 16;" :: "r"(sa), "l"(g));
}
__device__ __forceinline__ void cp_commit() { asm volatile("cp.async.commit_group;"); }
__device__ __forceinline__ void cp_wait0()  { asm volatile("cp.async.wait_group 0;"); }

__device__ __forceinline__ void ldm4(uint32_t* r, const void* p) {
    uint32_t a = (uint32_t)__cvta_generic_to_shared(p);
    asm volatile("ldmatrix.sync.aligned.m8n8.x4.shared.b16 {%0,%1,%2,%3}, [%4];"
                 : "=r"(r[0]), "=r"(r[1]), "=r"(r[2]), "=r"(r[3]) : "r"(a));
}
__device__ __forceinline__ void ldm4t(uint32_t* r, const void* p) {
    uint32_t a = (uint32_t)__cvta_generic_to_shared(p);
    asm volatile("ldmatrix.sync.aligned.m8n8.x4.trans.shared.b16 {%0,%1,%2,%3}, [%4];"
                 : "=r"(r[0]), "=r"(r[1]), "=r"(r[2]), "=r"(r[3]) : "r"(a));
}
__device__ __forceinline__ void mma_bf16(float* c, const uint32_t* a, const uint32_t* b) {
    asm volatile("mma.sync.aligned.m16n8k16.row.col.f32.bf16.bf16.f32 "
                 "{%0,%1,%2,%3}, {%4,%5,%6,%7}, {%8,%9}, {%0,%1,%2,%3};"
                 : "+f"(c[0]), "+f"(c[1]), "+f"(c[2]), "+f"(c[3])
                 : "r"(a[0]), "r"(a[1]), "r"(a[2]), "r"(a[3]),
                   "r"(b[0]), "r"(b[1]));
}
// pack two fp32 -> bf16x2 (lo in bits[15:0])
__device__ __forceinline__ uint32_t pk2(float lo, float hi) {
    uint32_t d;
    asm("cvt.rn.bf16x2.f32 %0, %1, %2;" : "=r"(d) : "f"(hi), "f"(lo));
    return d;
}
__device__ __forceinline__ uint32_t pk2_res(float a, float b, uint32_t hp) {
    __nv_bfloat162 h = *(__nv_bfloat162*)&hp;
    return pk2(a - __bfloat162float(h.x), b - __bfloat162float(h.y));
}

// ---------------- fp32 -> (hi, lo) bf16 split, vectorized -------------------
__global__ __launch_bounds__(256) void cvt_split(
    const float* __restrict__ in, __nv_bfloat16* __restrict__ hi,
    __nv_bfloat16* __restrict__ lo, int n)
{
    int i = (blockIdx.x * 256 + threadIdx.x) * 4;
    if (i >= n) return;
    float4 v = *(const float4*)(in + i);
    float vv[4] = {v.x, v.y, v.z, v.w};
    union { __nv_bfloat16 b[4]; uint2 u; } H, L;
#pragma unroll
    for (int j = 0; j < 4; j++) {
        __nv_bfloat16 h = __float2bfloat16(vv[j]);
        float r = vv[j] - __bfloat162float(h);
        H.b[j] = h;
        L.b[j] = __float2bfloat16(r);
    }
    *(uint2*)(hi + i) = H.u;
    *(uint2*)(lo + i) = L.u;
}

// ---------------- bf16x3 split-precision MMA GEMM (unchanged) ---------------
#define BM 128
#define BN 128
#define BK 32
#define SST 40
#define MATE (128 * SST)

__global__ __launch_bounds__(256, 1) void mma_gemm_nt(
    const __nv_bfloat16* __restrict__ Ah, const __nv_bfloat16* __restrict__ Al,
    const __nv_bfloat16* __restrict__ Bh, const __nv_bfloat16* __restrict__ Bl,
    const float* __restrict__ bias, float* __restrict__ C,
    int M, int N, int K)
{
    extern __shared__ __nv_bfloat16 smg[];
    int tid = threadIdx.x, lane = tid & 31, wid = tid >> 5;
    int wm = wid & 3, wn = wid >> 2;
    int bm = blockIdx.y * BM, bn = blockIdx.x * BN;

    float acc[2][8][4];
#pragma unroll
    for (int t = 0; t < 2; t++)
#pragma unroll
        for (int nn = 0; nn < 8; nn++)
#pragma unroll
            for (int q = 0; q < 4; q++) acc[t][nn][q] = 0.f;

    auto load_stage = [&](int st, int k0) {
        __nv_bfloat16* base = smg + st * 4 * MATE;
#pragma unroll
        for (int i = 0; i < 2; i++) {
            int c = tid + i * 256;
            int row = c >> 2, ch = (c & 3) * 8;
            int so = row * SST + ch;
            size_t goA = (size_t)(bm + row) * K + k0 + ch;
            size_t goB = (size_t)(bn + row) * K + k0 + ch;
            cp16(base + so,            Ah + goA);
            cp16(base + MATE + so,     Al + goA);
            cp16(base + 2 * MATE + so, Bh + goB);
            cp16(base + 3 * MATE + so, Bl + goB);
        }
    };

    load_stage(0, 0);
    cp_commit();

    int mrow = (lane & 7) + ((lane >> 3) & 1) * 8;
    int kcA  = (lane >> 4) * 8;
    int nrow = (lane & 7) + ((lane >> 4) & 1) * 8;
    int kcB  = ((lane >> 3) & 1) * 8;

    int nst = K / BK;
    for (int s = 0; s < nst; s++) {
        cp_wait0();
        __syncthreads();
        if (s + 1 < nst) { load_stage((s + 1) & 1, (s + 1) * BK); cp_commit(); }
        __nv_bfloat16* base = smg + (s & 1) * 4 * MATE;

#pragma unroll
        for (int kk = 0; kk < BK; kk += 16) {
            uint32_t ahf[2][4], alf[2][4];
#pragma unroll
            for (int t = 0; t < 2; t++) {
                const __nv_bfloat16* pa =
                    base + (wm * 32 + t * 16 + mrow) * SST + kk + kcA;
                ldm4(ahf[t], pa);
                ldm4(alf[t], pa + MATE);
            }
            uint32_t bhf[8][2], blf[8][2];
#pragma unroll
            for (int p = 0; p < 4; p++) {
                const __nv_bfloat16* pb =
                    base + 2 * MATE + (wn * 64 + p * 16 + nrow) * SST + kk + kcB;
                uint32_t r[4];
                ldm4(r, pb);
                bhf[2*p][0] = r[0]; bhf[2*p][1] = r[1];
                bhf[2*p+1][0] = r[2]; bhf[2*p+1][1] = r[3];
                ldm4(r, pb + MATE);
                blf[2*p][0] = r[0]; blf[2*p][1] = r[1];
                blf[2*p+1][0] = r[2]; blf[2*p+1][1] = r[3];
            }
#pragma unroll
            for (int t = 0; t < 2; t++)
#pragma unroll
                for (int nn = 0; nn < 8; nn++) {
                    mma_bf16(acc[t][nn], ahf[t], bhf[nn]);
                    mma_bf16(acc[t][nn], alf[t], bhf[nn]);
                    mma_bf16(acc[t][nn], ahf[t], blf[nn]);
                }
        }
    }

    int r0 = bm + wm * 32 + (lane >> 2);
    int c0 = bn + wn * 64 + (lane & 3) * 2;
#pragma unroll
    for (int t = 0; t < 2; t++) {
        int row = r0 + t * 16;
#pragma unroll
        for (int nn = 0; nn < 8; nn++) {
            int col = c0 + nn * 8;
            float b0 = bias ? bias[col] : 0.f;
            float b1 = bias ? bias[col + 1] : 0.f;
            *(float2*)(C + (size_t)row * N + col) =
                make_float2(acc[t][nn][0] + b0, acc[t][nn][1] + b1);
            *(float2*)(C + (size_t)(row + 8) * N + col) =
                make_float2(acc[t][nn][2] + b0, acc[t][nn][3] + b1);
        }
    }
}

// ---------------- LayerNorm on Q,K + split to hi/lo bf16 [B,H,N,d] ----------
// Q additionally prescaled by d^-0.5 = 0.125 (exact power of two).
__global__ __launch_bounds__(256) void ln_split(
    const float* __restrict__ qkv,
    const float* __restrict__ qg, const float* __restrict__ qb,
    const float* __restrict__ kg, const float* __restrict__ kb,
    __nv_bfloat16* __restrict__ Qh, __nv_bfloat16* __restrict__ Ql,
    __nv_bfloat16* __restrict__ Kh, __nv_bfloat16* __restrict__ Kl,
    __nv_bfloat16* __restrict__ Vh, __nv_bfloat16* __restrict__ Vl)
{
    int gw = (blockIdx.x * 256 + threadIdx.x) >> 5;
    int lane = threadIdx.x & 31;
    if (gw >= MROWS * NHEADS) return;
    int m = gw >> 4, h = gw & 15;
    int b = m >> 11, n = m & 2047;
    const float* row = qkv + (size_t)m * (3 * CDIM);
    size_t obase = ((size_t)(b * NHEADS + h) * SEQ + n) * HDIM;

    auto split_store = [&](__nv_bfloat16* H, __nv_bfloat16* L, size_t idx, float v) {
        __nv_bfloat16 hh = __float2bfloat16(v);
        H[idx] = hh;
        L[idx] = __float2bfloat16(v - __bfloat162float(hh));
    };

    {
        float v0 = row[h * 64 + lane], v1 = row[h * 64 + 32 + lane];
        float s = v0 + v1, ss = v0 * v0 + v1 * v1;
#pragma unroll
        for (int o = 16; o > 0; o >>= 1) {
            s  += __shfl_xor_sync(0xffffffffu, s,  o);
            ss += __shfl_xor_sync(0xffffffffu, ss, o);
        }
        float mu  = s * (1.f / 64.f);
        float var = ss * (1.f / 64.f) - mu * mu;
        float r = rsqrtf(var + 1e-5f);
        float o0 = ((v0 - mu) * r * qg[lane]      + qb[lane])      * 0.125f;
        float o1 = ((v1 - mu) * r * qg[32 + lane] + qb[32 + lane]) * 0.125f;
        split_store(Qh, Ql, obase + lane, o0);
        split_store(Qh, Ql, obase + 32 + lane, o1);
    }
    {
        float v0 = row[CDIM + h * 64 + lane], v1 = row[CDIM + h * 64 + 32 + lane];
        float s = v0 + v1, ss = v0 * v0 + v1 * v1;
#pragma unroll
        for (int o = 16; o > 0; o >>= 1) {
            s  += __shfl_xor_sync(0xffffffffu, s,  o);
            ss += __shfl_xor_sync(0xffffffffu, ss, o);
        }
        float mu  = s * (1.f / 64.f);
        float var = ss * (1.f / 64.f) - mu * mu;
        float r = rsqrtf(var + 1e-5f);
        float o0 = (v0 - mu) * r * kg[lane]      + kb[lane];
        float o1 = (v1 - mu) * r * kg[32 + lane] + kb[32 + lane];
        split_store(Kh, Kl, obase + lane, o0);
        split_store(Kh, Kl, obase + 32 + lane, o1);
    }
    split_store(Vh, Vl, obase + lane,      row[2 * CDIM + h * 64 + lane]);
    split_store(Vh, Vl, obase + 32 + lane, row[2 * CDIM + h * 64 + 32 + lane]);
}

// ---------------- flash attention, bf16x3 tensor-core, BQ=BK=64, d=64 -------
// 128 threads = 4 warps; warp w owns Q rows [w*16, w*16+16).
#define FA_ST 72                    // smem row stride (bf16 elems), bank-safe
#define FA_MAT (64 * FA_ST)         // 4608 elems = 9216 B
#define FA_STAGE 40960              // 4 matrices (K/V hi/lo) + 4096 B mask

__global__ __launch_bounds__(128) void flash_mma(
    const __nv_bfloat16* __restrict__ Qh_, const __nv_bfloat16* __restrict__ Ql_,
    const __nv_bfloat16* __restrict__ Kh_, const __nv_bfloat16* __restrict__ Kl_,
    const __nv_bfloat16* __restrict__ Vh_, const __nv_bfloat16* __restrict__ Vl_,
    const unsigned char* __restrict__ mask,
    __nv_bfloat16* __restrict__ Oh_, __nv_bfloat16* __restrict__ Ol_)
{
    extern __shared__ unsigned char smf[];
    int tid = threadIdx.x, lane = tid & 31, w = tid >> 5;
    int q0 = blockIdx.x * 64, h = blockIdx.y, b = blockIdx.z;
    size_t hb = (size_t)(b * NHEADS + h) * SEQ;
    const __nv_bfloat16* Qhp = Qh_ + (hb + q0) * HDIM;
    const __nv_bfloat16* Qlp = Ql_ + (hb + q0) * HDIM;
    const __nv_bfloat16* Kgh = Kh_ + hb * HDIM;
    const __nv_bfloat16* Kgl = Kl_ + hb * HDIM;
    const __nv_bfloat16* Vgh = Vh_ + hb * HDIM;
    const __nv_bfloat16* Vgl = Vl_ + hb * HDIM;
    const unsigned char* Mg = mask + ((size_t)b * SEQ + q0) * SEQ;

    int r0 = lane >> 2, cc = (lane & 3) * 2;

    // Q fragments in registers (hi/lo), 4 k-steps
    uint32_t qfh[4][4], qfl[4][4];
#pragma unroll
    for (int ks = 0; ks < 4; ks++) {
        int rA = w * 16 + r0;
        int kc = ks * 16 + cc;
        qfh[ks][0] = *(const uint32_t*)(Qhp + (size_t)rA * HDIM + kc);
        qfh[ks][1] = *(const uint32_t*)(Qhp + (size_t)(rA + 8) * HDIM + kc);
        qfh[ks][2] = *(const uint32_t*)(Qhp + (size_t)rA * HDIM + kc + 8);
        qfh[ks][3] = *(const uint32_t*)(Qhp + (size_t)(rA + 8) * HDIM + kc + 8);
        qfl[ks][0] = *(const uint32_t*)(Qlp + (size_t)rA * HDIM + kc);
        qfl[ks][1] = *(const uint32_t*)(Qlp + (size_t)(rA + 8) * HDIM + kc);
        qfl[ks][2] = *(const uint32_t*)(Qlp + (size_t)rA * HDIM + kc + 8);
        qfl[ks][3] = *(const uint32_t*)(Qlp + (size_t)(rA + 8) * HDIM + kc + 8);
    }

    float of[8][4];
#pragma unroll
    for (int j = 0; j < 8; j++)
#pragma unroll
        for (int e = 0; e < 4; e++) of[j][e] = 0.f;
    float mi0 = -FLT_MAX, mi1 = -FLT_MAX, li0 = 0.f, li1 = 0.f;

    auto load_stage = [&](int st, int kt) {
        unsigned char* base = smf + st * FA_STAGE;
        __nv_bfloat16* Ksh = (__nv_bfloat16*)base;
        __nv_bfloat16* Ksl = Ksh + FA_MAT;
        __nv_bfloat16* Vsh = Ksl + FA_MAT;
        __nv_bfloat16* Vsl = Vsh + FA_MAT;
        unsigned char* Ms  = base + 4 * FA_MAT * 2;
#pragma unroll
        for (int i = 0; i < 4; i++) {
            int c = tid + i * 128;          // 0..511
            int r = c >> 3, cl = (c & 7) * 8;
            size_t go = (size_t)(kt * 64 + r) * HDIM + cl;
            int so = r * FA_ST + cl;
            cp16(Ksh + so, Kgh + go);
            cp16(Ksl + so, Kgl + go);
            cp16(Vsh + so, Vgh + go);
            cp16(Vsl + so, Vgl + go);
        }
#pragma unroll
        for (int i = 0; i < 2; i++) {
            int c = tid + i * 128;          // 0..255
            int r = c >> 2, cl = (c & 3) * 16;
            cp16(Ms + r * 64 + cl, Mg + (size_t)r * SEQ + kt * 64 + cl);
        }
    };

    // B-operand lane mapping (identical to verified GEMM mapping)
    int nrowB = (lane & 7) + ((lane >> 4) & 1) * 8;
    int kcB   = ((lane >> 3) & 1) * 8;
    // V (trans) lane mapping
    int vrow  = ((lane >> 3) & 1) * 8 + (lane & 7);
    int vcol  = (lane >> 4) * 8;

    load_stage(0, 0);
    cp_commit();

    for (int kt = 0; kt < SEQ / 64; kt++) {
        cp_wait0();
        __syncthreads();
        unsigned char* base = smf + (kt & 1) * FA_STAGE;
        __nv_bfloat16* Ksh = (__nv_bfloat16*)base;
        __nv_bfloat16* Ksl = Ksh + FA_MAT;
        __nv_bfloat16* Vsh = Ksl + FA_MAT;
        __nv_bfloat16* Vsl = Vsh + FA_MAT;
        unsigned char* Ms  = base + 4 * FA_MAT * 2;

        // block-level mask detection (also a barrier)
        int om = 0;
        const uint32_t* mw = (const uint32_t*)Ms;
#pragma unroll
        for (int i = 0; i < 8; i++) om |= mw[tid * 8 + i];
        int anym = __syncthreads_or(om);

        if (kt + 1 < SEQ / 64) { load_stage((kt + 1) & 1, kt + 1); cp_commit(); }

        // ---- S = Q K^T (bf16x3) ----
        float sf[8][4];
#pragma unroll
        for (int j = 0; j < 8; j++)
#pragma unroll
            for (int e = 0; e < 4; e++) sf[j][e] = 0.f;

#pragma unroll
        for (int ks = 0; ks < 4; ks++) {
            uint32_t kbh[8][2], kbl[8][2];
#pragma unroll
            for (int p = 0; p < 4; p++) {
                const __nv_bfloat16* pb = Ksh + (p * 16 + nrowB) * FA_ST + ks * 16 + kcB;
                uint32_t r[4];
                ldm4(r, pb);
                kbh[2*p][0] = r[0]; kbh[2*p][1] = r[1];
                kbh[2*p+1][0] = r[2]; kbh[2*p+1][1] = r[3];
                ldm4(r, pb + FA_MAT);
                kbl[2*p][0] = r[0]; kbl[2*p][1] = r[1];
                kbl[2*p+1][0] = r[2]; kbl[2*p+1][1] = r[3];
            }
#pragma unroll
            for (int j = 0; j < 8; j++) {
                mma_bf16(sf[j], qfh[ks], kbh[j]);
                mma_bf16(sf[j], qfl[ks], kbh[j]);
                mma_bf16(sf[j], qfh[ks], kbl[j]);
            }
        }

        // ---- mask ----
        if (anym) {
            int rb0 = (w * 16 + r0) * 64, rb1 = rb0 + 8 * 64;
#pragma unroll
            for (int j = 0; j < 8; j++) {
                int colb = j * 8 + cc;
                if (Ms[rb0 + colb])     sf[j][0] = -FLT_MAX;
                if (Ms[rb0 + colb + 1]) sf[j][1] = -FLT_MAX;
                if (Ms[rb1 + colb])     sf[j][2] = -FLT_MAX;
                if (Ms[rb1 + colb + 1]) sf[j][3] = -FLT_MAX;
            }
        }

        // ---- online softmax (rows r0 and r0+8; quad = 4 lanes per row) ----
        float mx0 = -FLT_MAX, mx1 = -FLT_MAX;
#pragma unroll
        for (int j = 0; j < 8; j++) {
            mx0 = fmaxf(mx0, fmaxf(sf[j][0], sf[j][1]));
            mx1 = fmaxf(mx1, fmaxf(sf[j][2], sf[j][3]));
        }
        mx0 = fmaxf(mx0, __shfl_xor_sync(0xffffffffu, mx0, 1));
        mx0 = fmaxf(mx0, __shfl_xor_sync(0xffffffffu, mx0, 2));
        mx1 = fmaxf(mx1, __shfl_xor_sync(0xffffffffu, mx1, 1));
        mx1 = fmaxf(mx1, __shfl_xor_sync(0xffffffffu, mx1, 2));
        float m0n = fmaxf(mi0, mx0), m1n = fmaxf(mi1, mx1);
        float al0 = __expf(mi0 - m0n), al1 = __expf(mi1 - m1n);
        float s0 = 0.f, s1 = 0.f;
#pragma unroll
        for (int j = 0; j < 8; j++) {
            sf[j][0] = __expf(sf[j][0] - m0n); s0 += sf[j][0];
            sf[j][1] = __expf(sf[j][1] - m0n); s0 += sf[j][1];
            sf[j][2] = __expf(sf[j][2] - m1n); s1 += sf[j][2];
            sf[j][3] = __expf(sf[j][3] - m1n); s1 += sf[j][3];
        }
        s0 += __shfl_xor_sync(0xffffffffu, s0, 1);
        s0 += __shfl_xor_sync(0xffffffffu, s0, 2);
        s1 += __shfl_xor_sync(0xffffffffu, s1, 1);
        s1 += __shfl_xor_sync(0xffffffffu, s1, 2);
        li0 = li0 * al0 + s0; mi0 = m0n;
        li1 = li1 * al1 + s1; mi1 = m1n;
#pragma unroll
        for (int j = 0; j < 8; j++) {
            of[j][0] *= al0; of[j][1] *= al0;
            of[j][2] *= al1; of[j][3] *= al1;
        }

        // ---- O += P V (bf16x3; P split in-register) ----
#pragma unroll
        for (int ks = 0; ks < 4; ks++) {
            int j0 = 2 * ks, j1 = 2 * ks + 1;
            uint32_t pah[4], pal[4];
            pah[0] = pk2(sf[j0][0], sf[j0][1]);
            pah[1] = pk2(sf[j0][2], sf[j0][3]);
            pah[2] = pk2(sf[j1][0], sf[j1][1]);
            pah[3] = pk2(sf[j1][2], sf[j1][3]);
            pal[0] = pk2_res(sf[j0][0], sf[j0][1], pah[0]);
            pal[1] = pk2_res(sf[j0][2], sf[j0][3], pah[1]);
            pal[2] = pk2_res(sf[j1][0], sf[j1][1], pah[2]);
            pal[3] = pk2_res(sf[j1][2], sf[j1][3], pah[3]);

            uint32_t vbh[8][2], vbl[8][2];
#pragma unroll
            for (int p = 0; p < 4; p++) {
                const __nv_bfloat16* pv = Vsh + (ks * 16 + vrow) * FA_ST + p * 16 + vcol;
                uint32_t r[4];
                ldm4t(r, pv);
                vbh[2*p][0] = r[0]; vbh[2*p][1] = r[1];
                vbh[2*p+1][0] = r[2]; vbh[2*p+1][1] = r[3];
                ldm4t(r, pv + FA_MAT);
                vbl[2*p][0] = r[0]; vbl[2*p][1] = r[1];
                vbl[2*p+1][0] = r[2]; vbl[2*p+1][1] = r[3];
            }
#pragma unroll
            for (int j = 0; j < 8; j++) {
                mma_bf16(of[j], pah, vbh[j]);
                mma_bf16(of[j], pal, vbh[j]);
                mma_bf16(of[j], pah, vbl[j]);
            }
        }
    }

    // ---- epilogue: O/l -> hi/lo bf16 in [B*N, C] layout ----
    float inv0 = 1.f / li0, inv1 = 1.f / li1;
    int row0 = q0 + w * 16 + r0;
#pragma unroll
    for (int j = 0; j < 8; j++) {
        int col = h * 64 + j * 8 + cc;
        size_t o0 = ((size_t)b * SEQ + row0) * CDIM + col;
        size_t o1 = o0 + (size_t)8 * CDIM;
        float v0 = of[j][0] * inv0, v1 = of[j][1] * inv0;
        float v2 = of[j][2] * inv1, v3 = of[j][3] * inv1;
        uint32_t h0 = pk2(v0, v1), h1 = pk2(v2, v3);
        *(uint32_t*)(Oh_ + o0) = h0;
        *(uint32_t*)(Oh_ + o1) = h1;
        *(uint32_t*)(Ol_ + o0) = pk2_res(v0, v1, h0);
        *(uint32_t*)(Ol_ + o1) = pk2_res(v2, v3, h1);
    }
}

// ---------------- launch ----------------------------------------------------
extern "C" void kernel_launch(void* const* d_in, const int* in_sizes, int n_in,
                              void* d_out, int out_size)
{
    const float*         x       = (const float*)d_in[0];
    const unsigned char* mask    = (const unsigned char*)d_in[1];
    const float*         w_qkv   = (const float*)d_in[2];
    const float*         w_proj  = (const float*)d_in[3];
    const float*         b_proj  = (const float*)d_in[4];
    const float*         q_gamma = (const float*)d_in[5];
    const float*         q_beta  = (const float*)d_in[6];
    const float*         k_gamma = (const float*)d_in[7];
    const float*         k_beta  = (const float*)d_in[8];
    float* out = (float*)d_out;

    float* qkv;
    __nv_bfloat16 *xh, *xl, *wqh, *wql, *wph, *wpl, *oh, *ol;
    __nv_bfloat16 *qh, *ql, *kh, *kl, *vh, *vl;
    cudaGetSymbolAddress((void**)&qkv, g_qkv);
    cudaGetSymbolAddress((void**)&xh,  g_xh);
    cudaGetSymbolAddress((void**)&xl,  g_xl);
    cudaGetSymbolAddress((void**)&wqh, g_wqh);
    cudaGetSymbolAddress((void**)&wql, g_wql);
    cudaGetSymbolAddress((void**)&wph, g_wph);
    cudaGetSymbolAddress((void**)&wpl, g_wpl);
    cudaGetSymbolAddress((void**)&oh,  g_oh);
    cudaGetSymbolAddress((void**)&ol,  g_ol);
    cudaGetSymbolAddress((void**)&qh,  g_qh);
    cudaGetSymbolAddress((void**)&ql,  g_ql);
    cudaGetSymbolAddress((void**)&kh,  g_kh);
    cudaGetSymbolAddress((void**)&kl,  g_kl);
    cudaGetSymbolAddress((void**)&vh,  g_vh);
    cudaGetSymbolAddress((void**)&vl,  g_vl);

    static bool attr_set = false;
    if (!attr_set) {
        cudaFuncSetAttribute(mma_gemm_nt,
            cudaFuncAttributeMaxDynamicSharedMemorySize, 2 * 4 * MATE * 2);
        cudaFuncSetAttribute(flash_mma,
            cudaFuncAttributeMaxDynamicSharedMemorySize, 2 * FA_STAGE);
        attr_set = true;
    }

    // 0) fp32 -> bf16 hi/lo splits for GEMM operands
    int nx = MROWS * CDIM;
    cvt_split<<<nx / 4 / 256, 256>>>(x, xh, xl, nx);
    int nwq = 3 * CDIM * CDIM;
    cvt_split<<<nwq / 4 / 256, 256>>>(w_qkv, wqh, wql, nwq);
    int nwp = CDIM * CDIM;
    cvt_split<<<nwp / 4 / 256, 256>>>(w_proj, wph, wpl, nwp);

    // 1) QKV GEMM (tensor cores, bf16x3)
    mma_gemm_nt<<<dim3(3 * CDIM / BN, MROWS / BM), 256, 2 * 4 * MATE * 2>>>(
        xh, xl, wqh, wql, nullptr, qkv, MROWS, 3 * CDIM, CDIM);

    // 2) LN(q),LN(k) + hi/lo split into [B,H,N,d]; q prescaled by 0.125
    ln_split<<<(MROWS * NHEADS * 32) / 256, 256>>>(
        qkv, q_gamma, q_beta, k_gamma, k_beta,
        qh, ql, kh, kl, vh, vl);

    // 3) flash attention (tensor cores, bf16x3) -> hi/lo bf16 O
    flash_mma<<<dim3(SEQ / 64, NHEADS, BATCH), 128, 2 * FA_STAGE>>>(
        qh, ql, kh, kl, vh, vl, mask, oh, ol);

    // 4) proj GEMM + bias (tensor cores, bf16x3)
    mma_gemm_nt<<<dim3(CDIM / BN, MROWS / BM), 256, 2 * 4 * MATE * 2>>>(
        oh, ol, wph, wpl, b_proj, out, MROWS, CDIM, CDIM);
}

// round 7
// speedup vs baseline: 2.6108x; 1.0264x over previous
#include <cuda_runtime.h>
#include <cuda_bf16.h>
#include <cstdint>
#include <cfloat>

#define NHEADS 16
#define BATCH  2
#define SEQ    2048
#define CDIM   1024
#define HDIM   64
#define MROWS  (BATCH*SEQ)   // 4096

// ---------------- scratch (device globals; no allocations allowed) ----------
__device__ float g_qkv[(size_t)MROWS * 3 * CDIM];                 // 48 MB
__device__ __nv_bfloat16 g_xh[(size_t)MROWS * CDIM];
__device__ __nv_bfloat16 g_xl[(size_t)MROWS * CDIM];
__device__ __nv_bfloat16 g_wqh[(size_t)3 * CDIM * CDIM];
__device__ __nv_bfloat16 g_wql[(size_t)3 * CDIM * CDIM];
__device__ __nv_bfloat16 g_wph[(size_t)CDIM * CDIM];
__device__ __nv_bfloat16 g_wpl[(size_t)CDIM * CDIM];
__device__ __nv_bfloat16 g_oh[(size_t)MROWS * CDIM];
__device__ __nv_bfloat16 g_ol[(size_t)MROWS * CDIM];
// per-head hi/lo bf16 Q,K,V in [B,H,N,d]
#define PHN ((size_t)BATCH * NHEADS * SEQ * HDIM)
__device__ __nv_bfloat16 g_qh[PHN];
__device__ __nv_bfloat16 g_ql[PHN];
__device__ __nv_bfloat16 g_kh[PHN];
__device__ __nv_bfloat16 g_kl[PHN];
__device__ __nv_bfloat16 g_vh[PHN];
__device__ __nv_bfloat16 g_vl[PHN];

// ---------------- small PTX helpers -----------------------------------------
__device__ __forceinline__ void cp16(void* s, const void* g) {
    uint32_t sa = (uint32_t)__cvta_generic_to_shared(s);
    asm volatile("cp.async.cg.shared.global [%0], [%1], 16;" :: "r"(sa), "l"(g));
}
__device__ __forceinline__ void cp_commit() { asm volatile("cp.async.commit_group;"); }
__device__ __forceinline__ void cp_wait0()  { asm volatile("cp.async.wait_group 0;"); }

__device__ __forceinline__ void ldm4(uint32_t* r, const void* p) {
    uint32_t a = (uint32_t)__cvta_generic_to_shared(p);
    asm volatile("ldmatrix.sync.aligned.m8n8.x4.shared.b16 {%0,%1,%2,%3}, [%4];"
                 : "=r"(r[0]), "=r"(r[1]), "=r"(r[2]), "=r"(r[3]) : "r"(a));
}
__device__ __forceinline__ void ldm4t(uint32_t* r, const void* p) {
    uint32_t a = (uint32_t)__cvta_generic_to_shared(p);
    asm volatile("ldmatrix.sync.aligned.m8n8.x4.trans.shared.b16 {%0,%1,%2,%3}, [%4];"
                 : "=r"(r[0]), "=r"(r[1]), "=r"(r[2]), "=r"(r[3]) : "r"(a));
}
__device__ __forceinline__ void mma_bf16(float* c, const uint32_t* a, const uint32_t* b) {
    asm volatile("mma.sync.aligned.m16n8k16.row.col.f32.bf16.bf16.f32 "
                 "{%0,%1,%2,%3}, {%4,%5,%6,%7}, {%8,%9}, {%0,%1,%2,%3};"
                 : "+f"(c[0]), "+f"(c[1]), "+f"(c[2]), "+f"(c[3])
                 : "r"(a[0]), "r"(a[1]), "r"(a[2]), "r"(a[3]),
                   "r"(b[0]), "r"(b[1]));
}
// pack two fp32 -> bf16x2 (lo in bits[15:0])
__device__ __forceinline__ uint32_t pk2(float lo, float hi) {
    uint32_t d;
    asm("cvt.rn.bf16x2.f32 %0, %1, %2;" : "=r"(d) : "f"(hi), "f"(lo));
    return d;
}
__device__ __forceinline__ uint32_t pk2_res(float a, float b, uint32_t hp) {
    __nv_bfloat162 h = *(__nv_bfloat162*)&hp;
    return pk2(a - __bfloat162float(h.x), b - __bfloat162float(h.y));
}

// ---------------- fp32 -> (hi, lo) bf16 split, vectorized -------------------
__global__ __launch_bounds__(256) void cvt_split(
    const float* __restrict__ in, __nv_bfloat16* __restrict__ hi,
    __nv_bfloat16* __restrict__ lo, int n)
{
    int i = (blockIdx.x * 256 + threadIdx.x) * 4;
    if (i >= n) return;
    float4 v = *(const float4*)(in + i);
    float vv[4] = {v.x, v.y, v.z, v.w};
    union { __nv_bfloat16 b[4]; uint2 u; } H, L;
#pragma unroll
    for (int j = 0; j < 4; j++) {
        __nv_bfloat16 h = __float2bfloat16(vv[j]);
        float r = vv[j] - __bfloat162float(h);
        H.b[j] = h;
        L.b[j] = __float2bfloat16(r);
    }
    *(uint2*)(hi + i) = H.u;
    *(uint2*)(lo + i) = L.u;
}

// ---------------- bf16x3 split-precision MMA GEMM ---------------------------
// C[M,N] = A[M,K] * B[N,K]^T (+bias). 2 CTAs/SM target (regs <= 128).
#define BM 128
#define BN 128
#define BK 32
#define SST 40
#define MATE (128 * SST)

__global__ __launch_bounds__(256, 2) void mma_gemm_nt(
    const __nv_bfloat16* __restrict__ Ah, const __nv_bfloat16* __restrict__ Al,
    const __nv_bfloat16* __restrict__ Bh, const __nv_bfloat16* __restrict__ Bl,
    const float* __restrict__ bias, float* __restrict__ C,
    int M, int N, int K)
{
    extern __shared__ __nv_bfloat16 smg[];
    int tid = threadIdx.x, lane = tid & 31, wid = tid >> 5;
    int wm = wid & 3, wn = wid >> 2;
    int bm = blockIdx.y * BM, bn = blockIdx.x * BN;

    float acc[2][8][4];
#pragma unroll
    for (int t = 0; t < 2; t++)
#pragma unroll
        for (int nn = 0; nn < 8; nn++)
#pragma unroll
            for (int q = 0; q < 4; q++) acc[t][nn][q] = 0.f;

    auto load_stage = [&](int st, int k0) {
        __nv_bfloat16* base = smg + st * 4 * MATE;
#pragma unroll
        for (int i = 0; i < 2; i++) {
            int c = tid + i * 256;
            int row = c >> 2, ch = (c & 3) * 8;
            int so = row * SST + ch;
            size_t goA = (size_t)(bm + row) * K + k0 + ch;
            size_t goB = (size_t)(bn + row) * K + k0 + ch;
            cp16(base + so,            Ah + goA);
            cp16(base + MATE + so,     Al + goA);
            cp16(base + 2 * MATE + so, Bh + goB);
            cp16(base + 3 * MATE + so, Bl + goB);
        }
    };

    load_stage(0, 0);
    cp_commit();

    int mrow = (lane & 7) + ((lane >> 3) & 1) * 8;
    int kcA  = (lane >> 4) * 8;
    int nrow = (lane & 7) + ((lane >> 4) & 1) * 8;
    int kcB  = ((lane >> 3) & 1) * 8;

    int nst = K / BK;
    for (int s = 0; s < nst; s++) {
        cp_wait0();
        __syncthreads();
        if (s + 1 < nst) { load_stage((s + 1) & 1, (s + 1) * BK); cp_commit(); }
        __nv_bfloat16* base = smg + (s & 1) * 4 * MATE;

#pragma unroll
        for (int kk = 0; kk < BK; kk += 16) {
            uint32_t ahf[2][4], alf[2][4];
#pragma unroll
            for (int t = 0; t < 2; t++) {
                const __nv_bfloat16* pa =
                    base + (wm * 32 + t * 16 + mrow) * SST + kk + kcA;
                ldm4(ahf[t], pa);
                ldm4(alf[t], pa + MATE);
            }
            // B fragments in two chunks of 4 nn -> lower live-register count
#pragma unroll
            for (int cch = 0; cch < 2; cch++) {
                uint32_t bhf[4][2], blf[4][2];
#pragma unroll
                for (int p = 0; p < 2; p++) {
                    const __nv_bfloat16* pb = base + 2 * MATE +
                        (wn * 64 + (cch * 2 + p) * 16 + nrow) * SST + kk + kcB;
                    uint32_t r[4];
                    ldm4(r, pb);
                    bhf[2*p][0] = r[0]; bhf[2*p][1] = r[1];
                    bhf[2*p+1][0] = r[2]; bhf[2*p+1][1] = r[3];
                    ldm4(r, pb + MATE);
                    blf[2*p][0] = r[0]; blf[2*p][1] = r[1];
                    blf[2*p+1][0] = r[2]; blf[2*p+1][1] = r[3];
                }
#pragma unroll
                for (int t = 0; t < 2; t++)
#pragma unroll
                    for (int nn = 0; nn < 4; nn++) {
                        float* ac = acc[t][cch * 4 + nn];
                        mma_bf16(ac, ahf[t], bhf[nn]);
                        mma_bf16(ac, alf[t], bhf[nn]);
                        mma_bf16(ac, ahf[t], blf[nn]);
                    }
            }
        }
    }

    int r0 = bm + wm * 32 + (lane >> 2);
    int c0 = bn + wn * 64 + (lane & 3) * 2;
#pragma unroll
    for (int t = 0; t < 2; t++) {
        int row = r0 + t * 16;
#pragma unroll
        for (int nn = 0; nn < 8; nn++) {
            int col = c0 + nn * 8;
            float b0 = bias ? bias[col] : 0.f;
            float b1 = bias ? bias[col + 1] : 0.f;
            *(float2*)(C + (size_t)row * N + col) =
                make_float2(acc[t][nn][0] + b0, acc[t][nn][1] + b1);
            *(float2*)(C + (size_t)(row + 8) * N + col) =
                make_float2(acc[t][nn][2] + b0, acc[t][nn][3] + b1);
        }
    }
}

// ---------------- LayerNorm on Q,K + split to hi/lo bf16 [B,H,N,d] ----------
__global__ __launch_bounds__(256) void ln_split(
    const float* __restrict__ qkv,
    const float* __restrict__ qg, const float* __restrict__ qb,
    const float* __restrict__ kg, const float* __restrict__ kb,
    __nv_bfloat16* __restrict__ Qh, __nv_bfloat16* __restrict__ Ql,
    __nv_bfloat16* __restrict__ Kh, __nv_bfloat16* __restrict__ Kl,
    __nv_bfloat16* __restrict__ Vh, __nv_bfloat16* __restrict__ Vl)
{
    int gw = (blockIdx.x * 256 + threadIdx.x) >> 5;
    int lane = threadIdx.x & 31;
    if (gw >= MROWS * NHEADS) return;
    int m = gw >> 4, h = gw & 15;
    int b = m >> 11, n = m & 2047;
    const float* row = qkv + (size_t)m * (3 * CDIM);
    size_t obase = ((size_t)(b * NHEADS + h) * SEQ + n) * HDIM;

    auto split_store = [&](__nv_bfloat16* H, __nv_bfloat16* L, size_t idx, float v) {
        __nv_bfloat16 hh = __float2bfloat16(v);
        H[idx] = hh;
        L[idx] = __float2bfloat16(v - __bfloat162float(hh));
    };

    {
        float v0 = row[h * 64 + lane], v1 = row[h * 64 + 32 + lane];
        float s = v0 + v1, ss = v0 * v0 + v1 * v1;
#pragma unroll
        for (int o = 16; o > 0; o >>= 1) {
            s  += __shfl_xor_sync(0xffffffffu, s,  o);
            ss += __shfl_xor_sync(0xffffffffu, ss, o);
        }
        float mu  = s * (1.f / 64.f);
        float var = ss * (1.f / 64.f) - mu * mu;
        float r = rsqrtf(var + 1e-5f);
        float o0 = ((v0 - mu) * r * qg[lane]      + qb[lane])      * 0.125f;
        float o1 = ((v1 - mu) * r * qg[32 + lane] + qb[32 + lane]) * 0.125f;
        split_store(Qh, Ql, obase + lane, o0);
        split_store(Qh, Ql, obase + 32 + lane, o1);
    }
    {
        float v0 = row[CDIM + h * 64 + lane], v1 = row[CDIM + h * 64 + 32 + lane];
        float s = v0 + v1, ss = v0 * v0 + v1 * v1;
#pragma unroll
        for (int o = 16; o > 0; o >>= 1) {
            s  += __shfl_xor_sync(0xffffffffu, s,  o);
            ss += __shfl_xor_sync(0xffffffffu, ss, o);
        }
        float mu  = s * (1.f / 64.f);
        float var = ss * (1.f / 64.f) - mu * mu;
        float r = rsqrtf(var + 1e-5f);
        float o0 = (v0 - mu) * r * kg[lane]      + kb[lane];
        float o1 = (v1 - mu) * r * kg[32 + lane] + kb[32 + lane];
        split_store(Kh, Kl, obase + lane, o0);
        split_store(Kh, Kl, obase + 32 + lane, o1);
    }
    split_store(Vh, Vl, obase + lane,      row[2 * CDIM + h * 64 + lane]);
    split_store(Vh, Vl, obase + 32 + lane, row[2 * CDIM + h * 64 + 32 + lane]);
}

// ---------------- flash attention, bf16x3 tensor-core, BQ=BK=64, d=64 -------
#define FA_ST 72
#define FA_MAT (64 * FA_ST)
#define FA_STAGE 40960

__global__ __launch_bounds__(128) void flash_mma(
    const __nv_bfloat16* __restrict__ Qh_, const __nv_bfloat16* __restrict__ Ql_,
    const __nv_bfloat16* __restrict__ Kh_, const __nv_bfloat16* __restrict__ Kl_,
    const __nv_bfloat16* __restrict__ Vh_, const __nv_bfloat16* __restrict__ Vl_,
    const unsigned char* __restrict__ mask,
    __nv_bfloat16* __restrict__ Oh_, __nv_bfloat16* __restrict__ Ol_)
{
    extern __shared__ unsigned char smf[];
    int tid = threadIdx.x, lane = tid & 31, w = tid >> 5;
    int q0 = blockIdx.x * 64, h = blockIdx.y, b = blockIdx.z;
    size_t hb = (size_t)(b * NHEADS + h) * SEQ;
    const __nv_bfloat16* Qhp = Qh_ + (hb + q0) * HDIM;
    const __nv_bfloat16* Qlp = Ql_ + (hb + q0) * HDIM;
    const __nv_bfloat16* Kgh = Kh_ + hb * HDIM;
    const __nv_bfloat16* Kgl = Kl_ + hb * HDIM;
    const __nv_bfloat16* Vgh = Vh_ + hb * HDIM;
    const __nv_bfloat16* Vgl = Vl_ + hb * HDIM;
    const unsigned char* Mg = mask + ((size_t)b * SEQ + q0) * SEQ;

    int r0 = lane >> 2, cc = (lane & 3) * 2;

    uint32_t qfh[4][4], qfl[4][4];
#pragma unroll
    for (int ks = 0; ks < 4; ks++) {
        int rA = w * 16 + r0;
        int kc = ks * 16 + cc;
        qfh[ks][0] = *(const uint32_t*)(Qhp + (size_t)rA * HDIM + kc);
        qfh[ks][1] = *(const uint32_t*)(Qhp + (size_t)(rA + 8) * HDIM + kc);
        qfh[ks][2] = *(const uint32_t*)(Qhp + (size_t)rA * HDIM + kc + 8);
        qfh[ks][3] = *(const uint32_t*)(Qhp + (size_t)(rA + 8) * HDIM + kc + 8);
        qfl[ks][0] = *(const uint32_t*)(Qlp + (size_t)rA * HDIM + kc);
        qfl[ks][1] = *(const uint32_t*)(Qlp + (size_t)(rA + 8) * HDIM + kc);
        qfl[ks][2] = *(const uint32_t*)(Qlp + (size_t)rA * HDIM + kc + 8);
        qfl[ks][3] = *(const uint32_t*)(Qlp + (size_t)(rA + 8) * HDIM + kc + 8);
    }

    float of[8][4];
#pragma unroll
    for (int j = 0; j < 8; j++)
#pragma unroll
        for (int e = 0; e < 4; e++) of[j][e] = 0.f;
    float mi0 = -FLT_MAX, mi1 = -FLT_MAX, li0 = 0.f, li1 = 0.f;

    auto load_stage = [&](int st, int kt) {
        unsigned char* base = smf + st * FA_STAGE;
        __nv_bfloat16* Ksh = (__nv_bfloat16*)base;
        __nv_bfloat16* Ksl = Ksh + FA_MAT;
        __nv_bfloat16* Vsh = Ksl + FA_MAT;
        __nv_bfloat16* Vsl = Vsh + FA_MAT;
        unsigned char* Ms  = base + 4 * FA_MAT * 2;
#pragma unroll
        for (int i = 0; i < 4; i++) {
            int c = tid + i * 128;
            int r = c >> 3, cl = (c & 7) * 8;
            size_t go = (size_t)(kt * 64 + r) * HDIM + cl;
            int so = r * FA_ST + cl;
            cp16(Ksh + so, Kgh + go);
            cp16(Ksl + so, Kgl + go);
            cp16(Vsh + so, Vgh + go);
            cp16(Vsl + so, Vgl + go);
        }
#pragma unroll
        for (int i = 0; i < 2; i++) {
            int c = tid + i * 128;
            int r = c >> 2, cl = (c & 3) * 16;
            cp16(Ms + r * 64 + cl, Mg + (size_t)r * SEQ + kt * 64 + cl);
        }
    };

    int nrowB = (lane & 7) + ((lane >> 4) & 1) * 8;
    int kcB   = ((lane >> 3) & 1) * 8;
    int vrow  = ((lane >> 3) & 1) * 8 + (lane & 7);
    int vcol  = (lane >> 4) * 8;

    load_stage(0, 0);
    cp_commit();

    for (int kt = 0; kt < SEQ / 64; kt++) {
        cp_wait0();
        __syncthreads();
        unsigned char* base = smf + (kt & 1) * FA_STAGE;
        __nv_bfloat16* Ksh = (__nv_bfloat16*)base;
        __nv_bfloat16* Vsh = Ksh + 2 * FA_MAT;
        unsigned char* Ms  = base + 4 * FA_MAT * 2;

        int om = 0;
        const uint32_t* mw = (const uint32_t*)Ms;
#pragma unroll
        for (int i = 0; i < 8; i++) om |= mw[tid * 8 + i];
        int anym = __syncthreads_or(om);

        if (kt + 1 < SEQ / 64) { load_stage((kt + 1) & 1, kt + 1); cp_commit(); }

        float sf[8][4];
#pragma unroll
        for (int j = 0; j < 8; j++)
#pragma unroll
            for (int e = 0; e < 4; e++) sf[j][e] = 0.f;

#pragma unroll
        for (int ks = 0; ks < 4; ks++) {
            uint32_t kbh[8][2], kbl[8][2];
#pragma unroll
            for (int p = 0; p < 4; p++) {
                const __nv_bfloat16* pb = Ksh + (p * 16 + nrowB) * FA_ST + ks * 16 + kcB;
                uint32_t r[4];
                ldm4(r, pb);
                kbh[2*p][0] = r[0]; kbh[2*p][1] = r[1];
                kbh[2*p+1][0] = r[2]; kbh[2*p+1][1] = r[3];
                ldm4(r, pb + FA_MAT);
                kbl[2*p][0] = r[0]; kbl[2*p][1] = r[1];
                kbl[2*p+1][0] = r[2]; kbl[2*p+1][1] = r[3];
            }
#pragma unroll
            for (int j = 0; j < 8; j++) {
                mma_bf16(sf[j], qfh[ks], kbh[j]);
                mma_bf16(sf[j], qfl[ks], kbh[j]);
                mma_bf16(sf[j], qfh[ks], kbl[j]);
            }
        }

        if (anym) {
            int rb0 = (w * 16 + r0) * 64, rb1 = rb0 + 8 * 64;
#pragma unroll
            for (int j = 0; j < 8; j++) {
                int colb = j * 8 + cc;
                if (Ms[rb0 + colb])     sf[j][0] = -FLT_MAX;
                if (Ms[rb0 + colb + 1]) sf[j][1] = -FLT_MAX;
                if (Ms[rb1 + colb])     sf[j][2] = -FLT_MAX;
                if (Ms[rb1 + colb + 1]) sf[j][3] = -FLT_MAX;
            }
        }

        float mx0 = -FLT_MAX, mx1 = -FLT_MAX;
#pragma unroll
        for (int j = 0; j < 8; j++) {
            mx0 = fmaxf(mx0, fmaxf(sf[j][0], sf[j][1]));
            mx1 = fmaxf(mx1, fmaxf(sf[j][2], sf[j][3]));
        }
        mx0 = fmaxf(mx0, __shfl_xor_sync(0xffffffffu, mx0, 1));
        mx0 = fmaxf(mx0, __shfl_xor_sync(0xffffffffu, mx0, 2));
        mx1 = fmaxf(mx1, __shfl_xor_sync(0xffffffffu, mx1, 1));
        mx1 = fmaxf(mx1, __shfl_xor_sync(0xffffffffu, mx1, 2));
        float m0n = fmaxf(mi0, mx0), m1n = fmaxf(mi1, mx1);
        float al0 = __expf(mi0 - m0n), al1 = __expf(mi1 - m1n);
        float s0 = 0.f, s1 = 0.f;
#pragma unroll
        for (int j = 0; j < 8; j++) {
            sf[j][0] = __expf(sf[j][0] - m0n); s0 += sf[j][0];
            sf[j][1] = __expf(sf[j][1] - m0n); s0 += sf[j][1];
            sf[j][2] = __expf(sf[j][2] - m1n); s1 += sf[j][2];
            sf[j][3] = __expf(sf[j][3] - m1n); s1 += sf[j][3];
        }
        s0 += __shfl_xor_sync(0xffffffffu, s0, 1);
        s0 += __shfl_xor_sync(0xffffffffu, s0, 2);
        s1 += __shfl_xor_sync(0xffffffffu, s1, 1);
        s1 += __shfl_xor_sync(0xffffffffu, s1, 2);
        li0 = li0 * al0 + s0; mi0 = m0n;
        li1 = li1 * al1 + s1; mi1 = m1n;
#pragma unroll
        for (int j = 0; j < 8; j++) {
            of[j][0] *= al0; of[j][1] *= al0;
            of[j][2] *= al1; of[j][3] *= al1;
        }

#pragma unroll
        for (int ks = 0; ks < 4; ks++) {
            int j0 = 2 * ks, j1 = 2 * ks + 1;
            uint32_t pah[4], pal[4];
            pah[0] = pk2(sf[j0][0], sf[j0][1]);
            pah[1] = pk2(sf[j0][2], sf[j0][3]);
            pah[2] = pk2(sf[j1][0], sf[j1][1]);
            pah[3] = pk2(sf[j1][2], sf[j1][3]);
            pal[0] = pk2_res(sf[j0][0], sf[j0][1], pah[0]);
            pal[1] = pk2_res(sf[j0][2], sf[j0][3], pah[1]);
            pal[2] = pk2_res(sf[j1][0], sf[j1][1], pah[2]);
            pal[3] = pk2_res(sf[j1][2], sf[j1][3], pah[3]);

            uint32_t vbh[8][2], vbl[8][2];
#pragma unroll
            for (int p = 0; p < 4; p++) {
                const __nv_bfloat16* pv = Vsh + (ks * 16 + vrow) * FA_ST + p * 16 + vcol;
                uint32_t r[4];
                ldm4t(r, pv);
                vbh[2*p][0] = r[0]; vbh[2*p][1] = r[1];
                vbh[2*p+1][0] = r[2]; vbh[2*p+1][1] = r[3];
                ldm4t(r, pv + FA_MAT);
                vbl[2*p][0] = r[0]; vbl[2*p][1] = r[1];
                vbl[2*p+1][0] = r[2]; vbl[2*p+1][1] = r[3];
            }
#pragma unroll
            for (int j = 0; j < 8; j++) {
                mma_bf16(of[j], pah, vbh[j]);
                mma_bf16(of[j], pal, vbh[j]);
                mma_bf16(of[j], pah, vbl[j]);
            }
        }
    }

    float inv0 = 1.f / li0, inv1 = 1.f / li1;
    int row0 = q0 + w * 16 + r0;
#pragma unroll
    for (int j = 0; j < 8; j++) {
        int col = h * 64 + j * 8 + cc;
        size_t o0 = ((size_t)b * SEQ + row0) * CDIM + col;
        size_t o1 = o0 + (size_t)8 * CDIM;
        float v0 = of[j][0] * inv0, v1 = of[j][1] * inv0;
        float v2 = of[j][2] * inv1, v3 = of[j][3] * inv1;
        uint32_t h0 = pk2(v0, v1), h1 = pk2(v2, v3);
        *(uint32_t*)(Oh_ + o0) = h0;
        *(uint32_t*)(Oh_ + o1) = h1;
        *(uint32_t*)(Ol_ + o0) = pk2_res(v0, v1, h0);
        *(uint32_t*)(Ol_ + o1) = pk2_res(v2, v3, h1);
    }
}

// ---------------- launch ----------------------------------------------------
extern "C" void kernel_launch(void* const* d_in, const int* in_sizes, int n_in,
                              void* d_out, int out_size)
{
    const float*         x       = (const float*)d_in[0];
    const unsigned char* mask    = (const unsigned char*)d_in[1];
    const float*         w_qkv   = (const float*)d_in[2];
    const float*         w_proj  = (const float*)d_in[3];
    const float*         b_proj  = (const float*)d_in[4];
    const float*         q_gamma = (const float*)d_in[5];
    const float*         q_beta  = (const float*)d_in[6];
    const float*         k_gamma = (const float*)d_in[7];
    const float*         k_beta  = (const float*)d_in[8];
    float* out = (float*)d_out;

    float* qkv;
    __nv_bfloat16 *xh, *xl, *wqh, *wql, *wph, *wpl, *oh, *ol;
    __nv_bfloat16 *qh, *ql, *kh, *kl, *vh, *vl;
    cudaGetSymbolAddress((void**)&qkv, g_qkv);
    cudaGetSymbolAddress((void**)&xh,  g_xh);
    cudaGetSymbolAddress((void**)&xl,  g_xl);
    cudaGetSymbolAddress((void**)&wqh, g_wqh);
    cudaGetSymbolAddress((void**)&wql, g_wql);
    cudaGetSymbolAddress((void**)&wph, g_wph);
    cudaGetSymbolAddress((void**)&wpl, g_wpl);
    cudaGetSymbolAddress((void**)&oh,  g_oh);
    cudaGetSymbolAddress((void**)&ol,  g_ol);
    cudaGetSymbolAddress((void**)&qh,  g_qh);
    cudaGetSymbolAddress((void**)&ql,  g_ql);
    cudaGetSymbolAddress((void**)&kh,  g_kh);
    cudaGetSymbolAddress((void**)&kl,  g_kl);
    cudaGetSymbolAddress((void**)&vh,  g_vh);
    cudaGetSymbolAddress((void**)&vl,  g_vl);

    static bool attr_set = false;
    if (!attr_set) {
        cudaFuncSetAttribute(mma_gemm_nt,
            cudaFuncAttributeMaxDynamicSharedMemorySize, 2 * 4 * MATE * 2);
        cudaFuncSetAttribute(flash_mma,
            cudaFuncAttributeMaxDynamicSharedMemorySize, 2 * FA_STAGE);
        attr_set = true;
    }

    // 0) fp32 -> bf16 hi/lo splits for GEMM operands
    int nx = MROWS * CDIM;
    cvt_split<<<nx / 4 / 256, 256>>>(x, xh, xl, nx);
    int nwq = 3 * CDIM * CDIM;
    cvt_split<<<nwq / 4 / 256, 256>>>(w_qkv, wqh, wql, nwq);
    int nwp = CDIM * CDIM;
    cvt_split<<<nwp / 4 / 256, 256>>>(w_proj, wph, wpl, nwp);

    // 1) QKV GEMM (tensor cores, bf16x3)
    mma_gemm_nt<<<dim3(3 * CDIM / BN, MROWS / BM), 256, 2 * 4 * MATE * 2>>>(
        xh, xl, wqh, wql, nullptr, qkv, MROWS, 3 * CDIM, CDIM);

    // 2) LN(q),LN(k) + hi/lo split into [B,H,N,d]; q prescaled by 0.125
    ln_split<<<(MROWS * NHEADS * 32) / 256, 256>>>(
        qkv, q_gamma, q_beta, k_gamma, k_beta,
        qh, ql, kh, kl, vh, vl);

    // 3) flash attention (tensor cores, bf16x3) -> hi/lo bf16 O
    flash_mma<<<dim3(SEQ / 64, NHEADS, BATCH), 128, 2 * FA_STAGE>>>(
        qh, ql, kh, kl, vh, vl, mask, oh, ol);

    // 4) proj GEMM + bias (tensor cores, bf16x3)
    mma_gemm_nt<<<dim3(CDIM / BN, MROWS / BM), 256, 2 * FA_STAGE * 0 + 2 * 4 * MATE * 2>>>(
        oh, ol, wph, wpl, b_proj, out, MROWS, CDIM, CDIM);
}

// round 9
// speedup vs baseline: 2.9202x; 1.1185x over previous
#include <cuda_runtime.h>
#include <cuda_bf16.h>
#include <cstdint>
#include <cfloat>

#define NHEADS 16
#define BATCH  2
#define SEQ    2048
#define CDIM   1024
#define HDIM   64
#define MROWS  (BATCH*SEQ)   // 4096

// ---------------- scratch (device globals; no allocations allowed) ----------
__device__ float g_qkv[(size_t)MROWS * 3 * CDIM];                 // 48 MB
__device__ __nv_bfloat16 g_xh[(size_t)MROWS * CDIM];
__device__ __nv_bfloat16 g_xl[(size_t)MROWS * CDIM];
__device__ __nv_bfloat16 g_wqh[(size_t)3 * CDIM * CDIM];
__device__ __nv_bfloat16 g_wql[(size_t)3 * CDIM * CDIM];
__device__ __nv_bfloat16 g_wph[(size_t)CDIM * CDIM];
__device__ __nv_bfloat16 g_wpl[(size_t)CDIM * CDIM];
__device__ __nv_bfloat16 g_oh[(size_t)MROWS * CDIM];
__device__ __nv_bfloat16 g_ol[(size_t)MROWS * CDIM];
// per-head hi/lo bf16 Q,K,V in [B,H,N,d]
#define PHN ((size_t)BATCH * NHEADS * SEQ * HDIM)
__device__ __nv_bfloat16 g_qh[PHN];
__device__ __nv_bfloat16 g_ql[PHN];
__device__ __nv_bfloat16 g_kh[PHN];
__device__ __nv_bfloat16 g_kl[PHN];
__device__ __nv_bfloat16 g_vh[PHN];
__device__ __nv_bfloat16 g_vl[PHN];

// ---------------- small PTX helpers -----------------------------------------
__device__ __forceinline__ void cp16(void* s, const void* g) {
    uint32_t sa = (uint32_t)__cvta_generic_to_shared(s);
    asm volatile("cp.async.cg.shared.global [%0], [%1], 16;" :: "r"(sa), "l"(g));
}
__device__ __forceinline__ void cp_commit() { asm volatile("cp.async.commit_group;"); }
__device__ __forceinline__ void cp_wait0()  { asm volatile("cp.async.wait_group 0;"); }

__device__ __forceinline__ void ldm4(uint32_t* r, const void* p) {
    uint32_t a = (uint32_t)__cvta_generic_to_shared(p);
    asm volatile("ldmatrix.sync.aligned.m8n8.x4.shared.b16 {%0,%1,%2,%3}, [%4];"
                 : "=r"(r[0]), "=r"(r[1]), "=r"(r[2]), "=r"(r[3]) : "r"(a));
}
__device__ __forceinline__ void ldm4t(uint32_t* r, const void* p) {
    uint32_t a = (uint32_t)__cvta_generic_to_shared(p);
    asm volatile("ldmatrix.sync.aligned.m8n8.x4.trans.shared.b16 {%0,%1,%2,%3}, [%4];"
                 : "=r"(r[0]), "=r"(r[1]), "=r"(r[2]), "=r"(r[3]) : "r"(a));
}
__device__ __forceinline__ void mma_bf16(float* c, const uint32_t* a, const uint32_t* b) {
    asm volatile("mma.sync.aligned.m16n8k16.row.col.f32.bf16.bf16.f32 "
                 "{%0,%1,%2,%3}, {%4,%5,%6,%7}, {%8,%9}, {%0,%1,%2,%3};"
                 : "+f"(c[0]), "+f"(c[1]), "+f"(c[2]), "+f"(c[3])
                 : "r"(a[0]), "r"(a[1]), "r"(a[2]), "r"(a[3]),
                   "r"(b[0]), "r"(b[1]));
}
__device__ __forceinline__ uint32_t pk2(float lo, float hi) {
    uint32_t d;
    asm("cvt.rn.bf16x2.f32 %0, %1, %2;" : "=r"(d) : "f"(hi), "f"(lo));
    return d;
}
__device__ __forceinline__ uint32_t pk2_res(float a, float b, uint32_t hp) {
    __nv_bfloat162 h = *(__nv_bfloat162*)&hp;
    return pk2(a - __bfloat162float(h.x), b - __bfloat162float(h.y));
}

// ---------------- fp32 -> (hi, lo) bf16 split, vectorized -------------------
__global__ __launch_bounds__(256) void cvt_split(
    const float* __restrict__ in, __nv_bfloat16* __restrict__ hi,
    __nv_bfloat16* __restrict__ lo, int n)
{
    int i = (blockIdx.x * 256 + threadIdx.x) * 4;
    if (i >= n) return;
    float4 v = *(const float4*)(in + i);
    float vv[4] = {v.x, v.y, v.z, v.w};
    union { __nv_bfloat16 b[4]; uint2 u; } H, L;
#pragma unroll
    for (int j = 0; j < 4; j++) {
        __nv_bfloat16 h = __float2bfloat16(vv[j]);
        float r = vv[j] - __bfloat162float(h);
        H.b[j] = h;
        L.b[j] = __float2bfloat16(r);
    }
    *(uint2*)(hi + i) = H.u;
    *(uint2*)(lo + i) = L.u;
}

// ---------------- bf16x3 split-precision MMA GEMM ---------------------------
// C[M,N] = A[M,K] * B[N,K]^T (+bias). 2 CTAs/SM (regs <= 128).
#define BM 128
#define BN 128
#define BK 32
#define SST 40
#define MATE (128 * SST)

__global__ __launch_bounds__(256, 2) void mma_gemm_nt(
    const __nv_bfloat16* __restrict__ Ah, const __nv_bfloat16* __restrict__ Al,
    const __nv_bfloat16* __restrict__ Bh, const __nv_bfloat16* __restrict__ Bl,
    const float* __restrict__ bias, float* __restrict__ C,
    int M, int N, int K)
{
    extern __shared__ __nv_bfloat16 smg[];
    int tid = threadIdx.x, lane = tid & 31, wid = tid >> 5;
    int wm = wid & 3, wn = wid >> 2;
    int bm = blockIdx.y * BM, bn = blockIdx.x * BN;

    float acc[2][8][4];
#pragma unroll
    for (int t = 0; t < 2; t++)
#pragma unroll
        for (int nn = 0; nn < 8; nn++)
#pragma unroll
            for (int q = 0; q < 4; q++) acc[t][nn][q] = 0.f;

    auto load_stage = [&](int st, int k0) {
        __nv_bfloat16* base = smg + st * 4 * MATE;
#pragma unroll
        for (int i = 0; i < 2; i++) {
            int c = tid + i * 256;
            int row = c >> 2, ch = (c & 3) * 8;
            int so = row * SST + ch;
            size_t goA = (size_t)(bm + row) * K + k0 + ch;
            size_t goB = (size_t)(bn + row) * K + k0 + ch;
            cp16(base + so,            Ah + goA);
            cp16(base + MATE + so,     Al + goA);
            cp16(base + 2 * MATE + so, Bh + goB);
            cp16(base + 3 * MATE + so, Bl + goB);
        }
    };

    load_stage(0, 0);
    cp_commit();

    int mrow = (lane & 7) + ((lane >> 3) & 1) * 8;
    int kcA  = (lane >> 4) * 8;
    int nrow = (lane & 7) + ((lane >> 4) & 1) * 8;
    int kcB  = ((lane >> 3) & 1) * 8;

    int nst = K / BK;
    for (int s = 0; s < nst; s++) {
        cp_wait0();
        __syncthreads();
        if (s + 1 < nst) { load_stage((s + 1) & 1, (s + 1) * BK); cp_commit(); }
        __nv_bfloat16* base = smg + (s & 1) * 4 * MATE;

#pragma unroll
        for (int kk = 0; kk < BK; kk += 16) {
            uint32_t ahf[2][4], alf[2][4];
#pragma unroll
            for (int t = 0; t < 2; t++) {
                const __nv_bfloat16* pa =
                    base + (wm * 32 + t * 16 + mrow) * SST + kk + kcA;
                ldm4(ahf[t], pa);
                ldm4(alf[t], pa + MATE);
            }
#pragma unroll
            for (int cch = 0; cch < 2; cch++) {
                uint32_t bhf[4][2], blf[4][2];
#pragma unroll
                for (int p = 0; p < 2; p++) {
                    const __nv_bfloat16* pb = base + 2 * MATE +
                        (wn * 64 + (cch * 2 + p) * 16 + nrow) * SST + kk + kcB;
                    uint32_t r[4];
                    ldm4(r, pb);
                    bhf[2*p][0] = r[0]; bhf[2*p][1] = r[1];
                    bhf[2*p+1][0] = r[2]; bhf[2*p+1][1] = r[3];
                    ldm4(r, pb + MATE);
                    blf[2*p][0] = r[0]; blf[2*p][1] = r[1];
                    blf[2*p+1][0] = r[2]; blf[2*p+1][1] = r[3];
                }
#pragma unroll
                for (int t = 0; t < 2; t++)
#pragma unroll
                    for (int nn = 0; nn < 4; nn++) {
                        float* ac = acc[t][cch * 4 + nn];
                        mma_bf16(ac, ahf[t], bhf[nn]);
                        mma_bf16(ac, alf[t], bhf[nn]);
                        mma_bf16(ac, ahf[t], blf[nn]);
                    }
            }
        }
    }

    int r0 = bm + wm * 32 + (lane >> 2);
    int c0 = bn + wn * 64 + (lane & 3) * 2;
#pragma unroll
    for (int t = 0; t < 2; t++) {
        int row = r0 + t * 16;
#pragma unroll
        for (int nn = 0; nn < 8; nn++) {
            int col = c0 + nn * 8;
            float b0 = bias ? bias[col] : 0.f;
            float b1 = bias ? bias[col + 1] : 0.f;
            *(float2*)(C + (size_t)row * N + col) =
                make_float2(acc[t][nn][0] + b0, acc[t][nn][1] + b1);
            *(float2*)(C + (size_t)(row + 8) * N + col) =
                make_float2(acc[t][nn][2] + b0, acc[t][nn][3] + b1);
        }
    }
}

// ---------------- LayerNorm on Q,K + split to hi/lo bf16 [B,H,N,d] ----------
__global__ __launch_bounds__(256) void ln_split(
    const float* __restrict__ qkv,
    const float* __restrict__ qg, const float* __restrict__ qb,
    const float* __restrict__ kg, const float* __restrict__ kb,
    __nv_bfloat16* __restrict__ Qh, __nv_bfloat16* __restrict__ Ql,
    __nv_bfloat16* __restrict__ Kh, __nv_bfloat16* __restrict__ Kl,
    __nv_bfloat16* __restrict__ Vh, __nv_bfloat16* __restrict__ Vl)
{
    int gw = (blockIdx.x * 256 + threadIdx.x) >> 5;
    int lane = threadIdx.x & 31;
    if (gw >= MROWS * NHEADS) return;
    int m = gw >> 4, h = gw & 15;
    int b = m >> 11, n = m & 2047;
    const float* row = qkv + (size_t)m * (3 * CDIM);
    size_t obase = ((size_t)(b * NHEADS + h) * SEQ + n) * HDIM;

    auto split_store = [&](__nv_bfloat16* H, __nv_bfloat16* L, size_t idx, float v) {
        __nv_bfloat16 hh = __float2bfloat16(v);
        H[idx] = hh;
        L[idx] = __float2bfloat16(v - __bfloat162float(hh));
    };

    {
        float v0 = row[h * 64 + lane], v1 = row[h * 64 + 32 + lane];
        float s = v0 + v1, ss = v0 * v0 + v1 * v1;
#pragma unroll
        for (int o = 16; o > 0; o >>= 1) {
            s  += __shfl_xor_sync(0xffffffffu, s,  o);
            ss += __shfl_xor_sync(0xffffffffu, ss, o);
        }
        float mu  = s * (1.f / 64.f);
        float var = ss * (1.f / 64.f) - mu * mu;
        float r = rsqrtf(var + 1e-5f);
        float o0 = ((v0 - mu) * r * qg[lane]      + qb[lane])      * 0.125f;
        float o1 = ((v1 - mu) * r * qg[32 + lane] + qb[32 + lane]) * 0.125f;
        split_store(Qh, Ql, obase + lane, o0);
        split_store(Qh, Ql, obase + 32 + lane, o1);
    }
    {
        float v0 = row[CDIM + h * 64 + lane], v1 = row[CDIM + h * 64 + 32 + lane];
        float s = v0 + v1, ss = v0 * v0 + v1 * v1;
#pragma unroll
        for (int o = 16; o > 0; o >>= 1) {
            s  += __shfl_xor_sync(0xffffffffu, s,  o);
            ss += __shfl_xor_sync(0xffffffffu, ss, o);
        }
        float mu  = s * (1.f / 64.f);
        float var = ss * (1.f / 64.f) - mu * mu;
        float r = rsqrtf(var + 1e-5f);
        float o0 = (v0 - mu) * r * kg[lane]      + kb[lane];
        float o1 = (v1 - mu) * r * kg[32 + lane] + kb[32 + lane];
        split_store(Kh, Kl, obase + lane, o0);
        split_store(Kh, Kl, obase + 32 + lane, o1);
    }
    split_store(Vh, Vl, obase + lane,      row[2 * CDIM + h * 64 + lane]);
    split_store(Vh, Vl, obase + 32 + lane, row[2 * CDIM + h * 64 + 32 + lane]);
}

// ---------------- flash attention, bf16x3, BQ=128, BK=64, 8 warps -----------
// Q-hi fragments in regs; Q-lo tile in smem (ldmatrix per k-step).
// K/V hi/lo + mask double-buffered via cp.async.
#define FA_ST 72
#define FA_MAT (64 * FA_ST)                   // K/V tile: 64 rows
#define FA_QBYTES (128 * FA_ST * 2)           // Q-lo tile: 18432 B
#define FA_MASKB (128 * 64)                   // 8192 B
#define FA_STAGE (4 * FA_MAT * 2 + FA_MASKB)  // 45056 B
#define FA_SMEM (FA_QBYTES + 2 * FA_STAGE)    // 108544 B

__global__ __launch_bounds__(256, 2) void flash_mma(
    const __nv_bfloat16* __restrict__ Qh_, const __nv_bfloat16* __restrict__ Ql_,
    const __nv_bfloat16* __restrict__ Kh_, const __nv_bfloat16* __restrict__ Kl_,
    const __nv_bfloat16* __restrict__ Vh_, const __nv_bfloat16* __restrict__ Vl_,
    const unsigned char* __restrict__ mask,
    __nv_bfloat16* __restrict__ Oh_, __nv_bfloat16* __restrict__ Ol_)
{
    extern __shared__ unsigned char smf[];
    __nv_bfloat16* Qls = (__nv_bfloat16*)smf;
    unsigned char* stg = smf + FA_QBYTES;

    int tid = threadIdx.x, lane = tid & 31, w = tid >> 5;     // w: 0..7
    int q0 = blockIdx.x * 128, h = blockIdx.y, b = blockIdx.z;
    size_t hb = (size_t)(b * NHEADS + h) * SEQ;
    const __nv_bfloat16* Qhp = Qh_ + (hb + q0) * HDIM;
    const __nv_bfloat16* Qlp = Ql_ + (hb + q0) * HDIM;
    const __nv_bfloat16* Kgh = Kh_ + hb * HDIM;
    const __nv_bfloat16* Kgl = Kl_ + hb * HDIM;
    const __nv_bfloat16* Vgh = Vh_ + hb * HDIM;
    const __nv_bfloat16* Vgl = Vl_ + hb * HDIM;
    const unsigned char* Mg = mask + ((size_t)b * SEQ + q0) * SEQ;

    int r0 = lane >> 2, cc = (lane & 3) * 2;

    // Q-lo tile -> smem (once)
#pragma unroll
    for (int i = 0; i < 4; i++) {
        int c = tid + i * 256;               // 0..1023
        int r = c >> 3, cl = (c & 7) * 8;
        cp16(Qls + r * FA_ST + cl, Qlp + (size_t)r * HDIM + cl);
    }

    // Q-hi fragments in registers, 4 k-steps
    uint32_t qfh[4][4];
#pragma unroll
    for (int ks = 0; ks < 4; ks++) {
        int rA = w * 16 + r0;
        int kc = ks * 16 + cc;
        qfh[ks][0] = *(const uint32_t*)(Qhp + (size_t)rA * HDIM + kc);
        qfh[ks][1] = *(const uint32_t*)(Qhp + (size_t)(rA + 8) * HDIM + kc);
        qfh[ks][2] = *(const uint32_t*)(Qhp + (size_t)rA * HDIM + kc + 8);
        qfh[ks][3] = *(const uint32_t*)(Qhp + (size_t)(rA + 8) * HDIM + kc + 8);
    }

    float of[8][4];
#pragma unroll
    for (int j = 0; j < 8; j++)
#pragma unroll
        for (int e = 0; e < 4; e++) of[j][e] = 0.f;
    float mi0 = -FLT_MAX, mi1 = -FLT_MAX, li0 = 0.f, li1 = 0.f;

    auto load_stage = [&](int st, int kt) {
        unsigned char* base = stg + st * FA_STAGE;
        __nv_bfloat16* Ksh = (__nv_bfloat16*)base;
        unsigned char* Ms  = base + 4 * FA_MAT * 2;
#pragma unroll
        for (int m = 0; m < 4; m++) {
            const __nv_bfloat16* src = (m == 0) ? Kgh : (m == 1) ? Kgl
                                      : (m == 2) ? Vgh : Vgl;
            __nv_bfloat16* dst = Ksh + m * FA_MAT;
#pragma unroll
            for (int i = 0; i < 2; i++) {
                int c = tid + i * 256;       // 0..511
                int r = c >> 3, cl = (c & 7) * 8;
                cp16(dst + r * FA_ST + cl,
                     src + (size_t)(kt * 64 + r) * HDIM + cl);
            }
        }
#pragma unroll
        for (int i = 0; i < 2; i++) {
            int c = tid + i * 256;           // 0..511
            int r = c >> 2, cl = (c & 3) * 16;
            cp16(Ms + r * 64 + cl, Mg + (size_t)r * SEQ + kt * 64 + cl);
        }
    };

    // fragment lane mappings
    int mrowA = (lane & 7) + ((lane >> 3) & 1) * 8;   // A-operand (Q-lo from smem)
    int kcA   = (lane >> 4) * 8;
    int nrowB = (lane & 7) + ((lane >> 4) & 1) * 8;   // B-operand (K)
    int kcB   = ((lane >> 3) & 1) * 8;
    int vrow  = ((lane >> 3) & 1) * 8 + (lane & 7);   // V (trans)
    int vcol  = (lane >> 4) * 8;

    load_stage(0, 0);
    cp_commit();

    for (int kt = 0; kt < SEQ / 64; kt++) {
        cp_wait0();
        __syncthreads();
        unsigned char* base = stg + (kt & 1) * FA_STAGE;
        __nv_bfloat16* Ksh = (__nv_bfloat16*)base;
        __nv_bfloat16* Vsh = Ksh + 2 * FA_MAT;
        unsigned char* Ms  = base + 4 * FA_MAT * 2;

        int om = 0;
        const uint32_t* mw = (const uint32_t*)Ms;
#pragma unroll
        for (int i = 0; i < 8; i++) om |= mw[tid * 8 + i];
        int anym = __syncthreads_or(om);

        if (kt + 1 < SEQ / 64) { load_stage((kt + 1) & 1, kt + 1); cp_commit(); }

        // ---- S = Q K^T (bf16x3; Q-lo fragment from smem) ----
        float sf[8][4];
#pragma unroll
        for (int j = 0; j < 8; j++)
#pragma unroll
            for (int e = 0; e < 4; e++) sf[j][e] = 0.f;

#pragma unroll
        for (int ks = 0; ks < 4; ks++) {
            uint32_t qlf[4];
            ldm4(qlf, Qls + (w * 16 + mrowA) * FA_ST + ks * 16 + kcA);
#pragma unroll
            for (int ch = 0; ch < 2; ch++) {
                uint32_t kbh[4][2], kbl[4][2];
#pragma unroll
                for (int p = 0; p < 2; p++) {
                    const __nv_bfloat16* pb =
                        Ksh + ((ch * 2 + p) * 16 + nrowB) * FA_ST + ks * 16 + kcB;
                    uint32_t r[4];
                    ldm4(r, pb);
                    kbh[2*p][0] = r[0]; kbh[2*p][1] = r[1];
                    kbh[2*p+1][0] = r[2]; kbh[2*p+1][1] = r[3];
                    ldm4(r, pb + FA_MAT);
                    kbl[2*p][0] = r[0]; kbl[2*p][1] = r[1];
                    kbl[2*p+1][0] = r[2]; kbl[2*p+1][1] = r[3];
                }
#pragma unroll
                for (int j = 0; j < 4; j++) {
                    float* ac = sf[ch * 4 + j];
                    mma_bf16(ac, qfh[ks], kbh[j]);
                    mma_bf16(ac, qlf,     kbh[j]);
                    mma_bf16(ac, qfh[ks], kbl[j]);
                }
            }
        }

        // ---- mask ----
        if (anym) {
            int rb0 = (w * 16 + r0) * 64, rb1 = rb0 + 8 * 64;
#pragma unroll
            for (int j = 0; j < 8; j++) {
                int colb = j * 8 + cc;
                if (Ms[rb0 + colb])     sf[j][0] = -FLT_MAX;
                if (Ms[rb0 + colb + 1]) sf[j][1] = -FLT_MAX;
                if (Ms[rb1 + colb])     sf[j][2] = -FLT_MAX;
                if (Ms[rb1 + colb + 1]) sf[j][3] = -FLT_MAX;
            }
        }

        // ---- online softmax ----
        float mx0 = -FLT_MAX, mx1 = -FLT_MAX;
#pragma unroll
        for (int j = 0; j < 8; j++) {
            mx0 = fmaxf(mx0, fmaxf(sf[j][0], sf[j][1]));
            mx1 = fmaxf(mx1, fmaxf(sf[j][2], sf[j][3]));
        }
        mx0 = fmaxf(mx0, __shfl_xor_sync(0xffffffffu, mx0, 1));
        mx0 = fmaxf(mx0, __shfl_xor_sync(0xffffffffu, mx0, 2));
        mx1 = fmaxf(mx1, __shfl_xor_sync(0xffffffffu, mx1, 1));
        mx1 = fmaxf(mx1, __shfl_xor_sync(0xffffffffu, mx1, 2));
        float m0n = fmaxf(mi0, mx0), m1n = fmaxf(mi1, mx1);
        float al0 = __expf(mi0 - m0n), al1 = __expf(mi1 - m1n);
        float s0 = 0.f, s1 = 0.f;
#pragma unroll
        for (int j = 0; j < 8; j++) {
            sf[j][0] = __expf(sf[j][0] - m0n); s0 += sf[j][0];
            sf[j][1] = __expf(sf[j][1] - m0n); s0 += sf[j][1];
            sf[j][2] = __expf(sf[j][2] - m1n); s1 += sf[j][2];
            sf[j][3] = __expf(sf[j][3] - m1n); s1 += sf[j][3];
        }
        s0 += __shfl_xor_sync(0xffffffffu, s0, 1);
        s0 += __shfl_xor_sync(0xffffffffu, s0, 2);
        s1 += __shfl_xor_sync(0xffffffffu, s1, 1);
        s1 += __shfl_xor_sync(0xffffffffu, s1, 2);
        li0 = li0 * al0 + s0; mi0 = m0n;
        li1 = li1 * al1 + s1; mi1 = m1n;
#pragma unroll
        for (int j = 0; j < 8; j++) {
            of[j][0] *= al0; of[j][1] *= al0;
            of[j][2] *= al1; of[j][3] *= al1;
        }

        // ---- O += P V (bf16x3; P split in-register) ----
#pragma unroll
        for (int ks = 0; ks < 4; ks++) {
            int j0 = 2 * ks, j1 = 2 * ks + 1;
            uint32_t pah[4], pal[4];
            pah[0] = pk2(sf[j0][0], sf[j0][1]);
            pah[1] = pk2(sf[j0][2], sf[j0][3]);
            pah[2] = pk2(sf[j1][0], sf[j1][1]);
            pah[3] = pk2(sf[j1][2], sf[j1][3]);
            pal[0] = pk2_res(sf[j0][0], sf[j0][1], pah[0]);
            pal[1] = pk2_res(sf[j0][2], sf[j0][3], pah[1]);
            pal[2] = pk2_res(sf[j1][0], sf[j1][1], pah[2]);
            pal[3] = pk2_res(sf[j1][2], sf[j1][3], pah[3]);

#pragma unroll
            for (int ch = 0; ch < 2; ch++) {
                uint32_t vbh[4][2], vbl[4][2];
#pragma unroll
                for (int p = 0; p < 2; p++) {
                    const __nv_bfloat16* pv = Vsh + (ks * 16 + vrow) * FA_ST
                                            + (ch * 2 + p) * 16 + vcol;
                    uint32_t r[4];
                    ldm4t(r, pv);
                    vbh[2*p][0] = r[0]; vbh[2*p][1] = r[1];
                    vbh[2*p+1][0] = r[2]; vbh[2*p+1][1] = r[3];
                    ldm4t(r, pv + FA_MAT);
                    vbl[2*p][0] = r[0]; vbl[2*p][1] = r[1];
                    vbl[2*p+1][0] = r[2]; vbl[2*p+1][1] = r[3];
                }
#pragma unroll
                for (int j = 0; j < 4; j++) {
                    float* ac = of[ch * 4 + j];
                    mma_bf16(ac, pah, vbh[j]);
                    mma_bf16(ac, pal, vbh[j]);
                    mma_bf16(ac, pah, vbl[j]);
                }
            }
        }
    }

    // ---- epilogue: O/l -> hi/lo bf16 in [B*N, C] layout ----
    float inv0 = 1.f / li0, inv1 = 1.f / li1;
    int row0 = q0 + w * 16 + r0;
#pragma unroll
    for (int j = 0; j < 8; j++) {
        int col = h * 64 + j * 8 + cc;
        size_t o0 = ((size_t)b * SEQ + row0) * CDIM + col;
        size_t o1 = o0 + (size_t)8 * CDIM;
        float v0 = of[j][0] * inv0, v1 = of[j][1] * inv0;
        float v2 = of[j][2] * inv1, v3 = of[j][3] * inv1;
        uint32_t h0 = pk2(v0, v1), h1 = pk2(v2, v3);
        *(uint32_t*)(Oh_ + o0) = h0;
        *(uint32_t*)(Oh_ + o1) = h1;
        *(uint32_t*)(Ol_ + o0) = pk2_res(v0, v1, h0);
        *(uint32_t*)(Ol_ + o1) = pk2_res(v2, v3, h1);
    }
}

// ---------------- launch ----------------------------------------------------
extern "C" void kernel_launch(void* const* d_in, const int* in_sizes, int n_in,
                              void* d_out, int out_size)
{
    const float*         x       = (const float*)d_in[0];
    const unsigned char* mask    = (const unsigned char*)d_in[1];
    const float*         w_qkv   = (const float*)d_in[2];
    const float*         w_proj  = (const float*)d_in[3];
    const float*         b_proj  = (const float*)d_in[4];
    const float*         q_gamma = (const float*)d_in[5];
    const float*         q_beta  = (const float*)d_in[6];
    const float*         k_gamma = (const float*)d_in[7];
    const float*         k_beta  = (const float*)d_in[8];
    float* out = (float*)d_out;

    float* qkv;
    __nv_bfloat16 *xh, *xl, *wqh, *wql, *wph, *wpl, *oh, *ol;
    __nv_bfloat16 *qh, *ql, *kh, *kl, *vh, *vl;
    cudaGetSymbolAddress((void**)&qkv, g_qkv);
    cudaGetSymbolAddress((void**)&xh,  g_xh);
    cudaGetSymbolAddress((void**)&xl,  g_xl);
    cudaGetSymbolAddress((void**)&wqh, g_wqh);
    cudaGetSymbolAddress((void**)&wql, g_wql);
    cudaGetSymbolAddress((void**)&wph, g_wph);
    cudaGetSymbolAddress((void**)&wpl, g_wpl);
    cudaGetSymbolAddress((void**)&oh,  g_oh);
    cudaGetSymbolAddress((void**)&ol,  g_ol);
    cudaGetSymbolAddress((void**)&qh,  g_qh);
    cudaGetSymbolAddress((void**)&ql,  g_ql);
    cudaGetSymbolAddress((void**)&kh,  g_kh);
    cudaGetSymbolAddress((void**)&kl,  g_kl);
    cudaGetSymbolAddress((void**)&vh,  g_vh);
    cudaGetSymbolAddress((void**)&vl,  g_vl);

    static bool attr_set = false;
    if (!attr_set) {
        cudaFuncSetAttribute(mma_gemm_nt,
            cudaFuncAttributeMaxDynamicSharedMemorySize, 2 * 4 * MATE * 2);
        cudaFuncSetAttribute(flash_mma,
            cudaFuncAttributeMaxDynamicSharedMemorySize, FA_SMEM);
        attr_set = true;
    }

    // 0) fp32 -> bf16 hi/lo splits for GEMM operands
    int nx = MROWS * CDIM;
    cvt_split<<<nx / 4 / 256, 256>>>(x, xh, xl, nx);
    int nwq = 3 * CDIM * CDIM;
    cvt_split<<<nwq / 4 / 256, 256>>>(w_qkv, wqh, wql, nwq);
    int nwp = CDIM * CDIM;
    cvt_split<<<nwp / 4 / 256, 256>>>(w_proj, wph, wpl, nwp);

    // 1) QKV GEMM (mma.sync, bf16x3)
    mma_gemm_nt<<<dim3(3 * CDIM / BN, MROWS / BM), 256, 2 * 4 * MATE * 2>>>(
        xh, xl, wqh, wql, nullptr, qkv, MROWS, 3 * CDIM, CDIM);

    // 2) LN(q),LN(k) + hi/lo split into [B,H,N,d]; q prescaled by 0.125
    ln_split<<<(MROWS * NHEADS * 32) / 256, 256>>>(
        qkv, q_gamma, q_beta, k_gamma, k_beta,
        qh, ql, kh, kl, vh, vl);

    // 3) flash attention (mma.sync, bf16x3), BQ=128 -> hi/lo bf16 O
    flash_mma<<<dim3(SEQ / 128, NHEADS, BATCH), 256, FA_SMEM>>>(
        qh, ql, kh, kl, vh, vl, mask, oh, ol);

    // 4) proj GEMM + bias (mma.sync, bf16x3)
    mma_gemm_nt<<<dim3(CDIM / BN, MROWS / BM), 256, 2 * 4 * MATE * 2>>>(
        oh, ol, wph, wpl, b_proj, out, MROWS, CDIM, CDIM);
}